// round 2
// baseline (speedup 1.0000x reference)
#include <cuda_runtime.h>
#include <cstdint>

#define BB 8
#define TT 1024
#define EE 1024
#define HH 16
#define HD 64
#define FFD 4096
#define MM (BB*TT)          // 8192 rows
#define SCALE 0.125f        // HD^-0.5

// ---------------- scratch (device globals: allocation-free) ----------------
static __device__ float g_qkv[MM * 3 * EE];   // 96 MB
static __device__ float g_attn[MM * EE];      // 32 MB
static __device__ float g_y1[MM * EE];        // 32 MB
static __device__ float g_ffh[MM * FFD];      // 128 MB
static __device__ int   g_mask_mode;          // 0=u8, 1=i32, 2=f32

// ---------------- mask dtype probe ----------------
// Scans the first 8192 bytes of the padding mask. Bool(uint8) runs of 1s touch
// arbitrary byte offsets mod 4; int32 value 1 puts nonzero bytes only at
// offset 0 mod 4; float32 1.0f only at offsets 2,3 (0x80,0x3F).
__global__ void probe_mask(const unsigned char* __restrict__ p) {
    __shared__ int cnt[4];
    if (threadIdx.x < 4) cnt[threadIdx.x] = 0;
    __syncthreads();
    int local[4] = {0, 0, 0, 0};
    for (int i = threadIdx.x; i < 8192; i += blockDim.x)
        if (p[i]) local[i & 3]++;
    #pragma unroll
    for (int c = 0; c < 4; c++)
        if (local[c]) atomicAdd(&cnt[c], local[c]);
    __syncthreads();
    if (threadIdx.x == 0) {
        int c0 = cnt[0], c1 = cnt[1], c2 = cnt[2], c3 = cnt[3];
        int mode = 0;
        if (c0 > 0 && c1 == 0 && c2 == 0 && c3 == 0) mode = 1;        // int32
        else if (c0 == 0 && c1 == 0 && (c2 > 0 || c3 > 0)) mode = 2;  // float32
        g_mask_mode = mode;
    }
}

// ---------------- SGEMM: C[M,N] = act(A[M,K] @ W[N,K]^T + bias (+R)) -------
// 128x128 tile, BK=8, 256 threads, 8x8 per thread.
#define GT 128
#define GK 8

template <bool RELU, bool RES>
__global__ __launch_bounds__(256) void gemm_nt(
    const float* __restrict__ A, const float* __restrict__ W,
    const float* __restrict__ bias, const float* __restrict__ R,
    float* __restrict__ C, int M, int N, int K)
{
    __shared__ float As[GK][GT];
    __shared__ float Bs[GK][GT];

    const int tid = threadIdx.x;
    const int m0 = blockIdx.y * GT;
    const int n0 = blockIdx.x * GT;

    const int lrow = tid >> 1;           // 0..127
    const int lcol = (tid & 1) * 4;      // 0 or 4
    const float* Aptr = A + (size_t)(m0 + lrow) * K + lcol;
    const float* Wptr = W + (size_t)(n0 + lrow) * K + lcol;

    const int ty = tid >> 4;             // 0..15
    const int tx = tid & 15;             // 0..15

    float acc[8][8];
    #pragma unroll
    for (int i = 0; i < 8; i++)
        #pragma unroll
        for (int j = 0; j < 8; j++) acc[i][j] = 0.f;

    for (int k0 = 0; k0 < K; k0 += GK) {
        float4 av = *(const float4*)(Aptr + k0);
        float4 wv = *(const float4*)(Wptr + k0);
        As[lcol + 0][lrow] = av.x; As[lcol + 1][lrow] = av.y;
        As[lcol + 2][lrow] = av.z; As[lcol + 3][lrow] = av.w;
        Bs[lcol + 0][lrow] = wv.x; Bs[lcol + 1][lrow] = wv.y;
        Bs[lcol + 2][lrow] = wv.z; Bs[lcol + 3][lrow] = wv.w;
        __syncthreads();

        #pragma unroll
        for (int kk = 0; kk < GK; kk++) {
            float a[8], b[8];
            *(float4*)&a[0] = *(const float4*)&As[kk][ty * 4];
            *(float4*)&a[4] = *(const float4*)&As[kk][64 + ty * 4];
            *(float4*)&b[0] = *(const float4*)&Bs[kk][tx * 4];
            *(float4*)&b[4] = *(const float4*)&Bs[kk][64 + tx * 4];
            #pragma unroll
            for (int i = 0; i < 8; i++)
                #pragma unroll
                for (int j = 0; j < 8; j++)
                    acc[i][j] += a[i] * b[j];
        }
        __syncthreads();
    }

    #pragma unroll
    for (int i = 0; i < 8; i++) {
        int m = m0 + ((i < 4) ? (ty * 4 + i) : (64 + ty * 4 + (i - 4)));
        #pragma unroll
        for (int jq = 0; jq < 2; jq++) {
            int n = n0 + ((jq == 0) ? (tx * 4) : (64 + tx * 4));
            float4 bv = *(const float4*)(bias + n);
            float4 v;
            v.x = acc[i][jq * 4 + 0] + bv.x;
            v.y = acc[i][jq * 4 + 1] + bv.y;
            v.z = acc[i][jq * 4 + 2] + bv.z;
            v.w = acc[i][jq * 4 + 3] + bv.w;
            if (RES) {
                float4 rv = *(const float4*)(R + (size_t)m * N + n);
                v.x += rv.x; v.y += rv.y; v.z += rv.z; v.w += rv.w;
            }
            if (RELU) {
                v.x = fmaxf(v.x, 0.f); v.y = fmaxf(v.y, 0.f);
                v.z = fmaxf(v.z, 0.f); v.w = fmaxf(v.w, 0.f);
            }
            *(float4*)(C + (size_t)m * N + n) = v;
        }
    }
}

// ---------------- flash attention (fp32, causal + padding) ----------------
// grid (qtile=16, head=16, batch=8), 64 threads, 1 thread = 1 query row.
__global__ __launch_bounds__(64) void attn_kernel(
    const float* __restrict__ qkv, const void* __restrict__ pad,
    float* __restrict__ out)
{
    __shared__ float Ks[64 * 64];
    __shared__ float Vs[64 * 64];
    __shared__ unsigned char pmask[64];

    const int qt = blockIdx.x, h = blockIdx.y, b = blockIdx.z;
    const int tid = threadIdx.x;
    const int tq = qt * 64 + tid;
    const int row3 = 3 * EE;
    const int mode = g_mask_mode;

    const float* qrow = qkv + (size_t)(b * TT + tq) * row3 + h * HD;
    float q[HD];
    #pragma unroll
    for (int d = 0; d < HD; d++) q[d] = qrow[d] * SCALE;

    float o[HD];
    #pragma unroll
    for (int d = 0; d < HD; d++) o[d] = 0.f;
    float mrun = -INFINITY, lrun = 0.f;

    const int nkt = qt + 1;  // causal: key tiles 0..qt
    for (int kt = 0; kt < nkt; kt++) {
        const int t0 = kt * 64;
        const float* kbase = qkv + (size_t)(b * TT + t0) * row3 + EE + h * HD;
        const float* vbase = kbase + EE;
        // stage K/V tiles
        #pragma unroll
        for (int r = 0; r < 16; r++) {
            int linear = r * 64 + tid;       // float4 index 0..1023
            int j = linear >> 4;
            int d4 = (linear & 15) * 4;
            *(float4*)&Ks[j * 64 + d4] = *(const float4*)(kbase + (size_t)j * row3 + d4);
            *(float4*)&Vs[j * 64 + d4] = *(const float4*)(vbase + (size_t)j * row3 + d4);
        }
        {
            int tk = t0 + tid;
            unsigned char pm;
            if (mode == 1)      pm = (((const int*)pad)[b * TT + tk] != 0);
            else if (mode == 2) pm = (((const float*)pad)[b * TT + tk] != 0.f);
            else                pm = (((const unsigned char*)pad)[b * TT + tk] != 0);
            pmask[tid] = pm;
        }
        __syncthreads();

        float s[64];
        float tmax = -INFINITY;
        for (int j = 0; j < 64; j++) {
            int tk = t0 + j;
            if (tk <= tq && !pmask[j]) {
                float a0 = 0.f, a1 = 0.f;
                #pragma unroll
                for (int d4 = 0; d4 < HD; d4 += 8) {
                    float4 k0v = *(const float4*)&Ks[j * 64 + d4];
                    float4 k1v = *(const float4*)&Ks[j * 64 + d4 + 4];
                    a0 += q[d4 + 0] * k0v.x + q[d4 + 1] * k0v.y
                        + q[d4 + 2] * k0v.z + q[d4 + 3] * k0v.w;
                    a1 += q[d4 + 4] * k1v.x + q[d4 + 5] * k1v.y
                        + q[d4 + 6] * k1v.z + q[d4 + 7] * k1v.w;
                }
                float a = a0 + a1;
                s[j] = a;
                tmax = fmaxf(tmax, a);
            } else {
                s[j] = -INFINITY;
            }
        }

        if (tmax != -INFINITY) {
            float mnew = fmaxf(mrun, tmax);
            float alpha = __expf(mrun - mnew);   // 0 when mrun == -inf
            lrun *= alpha;
            #pragma unroll
            for (int d = 0; d < HD; d++) o[d] *= alpha;
            for (int j = 0; j < 64; j++) {
                float p = __expf(s[j] - mnew);   // 0 for masked entries
                lrun += p;
                #pragma unroll
                for (int d4 = 0; d4 < HD; d4 += 4) {
                    float4 vv = *(const float4*)&Vs[j * 64 + d4];
                    o[d4 + 0] += p * vv.x; o[d4 + 1] += p * vv.y;
                    o[d4 + 2] += p * vv.z; o[d4 + 3] += p * vv.w;
                }
            }
            mrun = mnew;
        }
        __syncthreads();
    }

    const float inv = 1.f / lrun;
    float* orow = out + (size_t)(b * TT + tq) * EE + h * HD;
    #pragma unroll
    for (int d = 0; d < HD; d++) orow[d] = o[d] * inv;
}

// ---------------- LayerNorm in-place, one block per row ----------------
__global__ __launch_bounds__(256) void ln_kernel(
    float* __restrict__ X, const float* __restrict__ w,
    const float* __restrict__ bias)
{
    __shared__ float red[8];
    const int row = blockIdx.x, tid = threadIdx.x;
    float4* xr = (float4*)(X + (size_t)row * EE);
    float4 v = xr[tid];

    float s = v.x + v.y + v.z + v.w;
    #pragma unroll
    for (int o = 16; o; o >>= 1) s += __shfl_xor_sync(0xffffffffu, s, o);
    if ((tid & 31) == 0) red[tid >> 5] = s;
    __syncthreads();
    float tot = red[0] + red[1] + red[2] + red[3] + red[4] + red[5] + red[6] + red[7];
    const float mean = tot * (1.f / EE);

    float dx = v.x - mean, dy = v.y - mean, dz = v.z - mean, dw = v.w - mean;
    float s2 = dx * dx + dy * dy + dz * dz + dw * dw;
    __syncthreads();  // protect red before reuse
    #pragma unroll
    for (int o = 16; o; o >>= 1) s2 += __shfl_xor_sync(0xffffffffu, s2, o);
    if ((tid & 31) == 0) red[tid >> 5] = s2;
    __syncthreads();
    float tot2 = red[0] + red[1] + red[2] + red[3] + red[4] + red[5] + red[6] + red[7];
    const float var = tot2 * (1.f / EE);
    const float inv = rsqrtf(var + 1e-12f);

    float4 wv = ((const float4*)w)[tid];
    float4 bv = ((const float4*)bias)[tid];
    float4 r;
    r.x = dx * inv * wv.x + bv.x;
    r.y = dy * inv * wv.y + bv.y;
    r.z = dz * inv * wv.z + bv.z;
    r.w = dw * inv * wv.w + bv.w;
    xr[tid] = r;
}

// ---------------- launch ----------------
extern "C" void kernel_launch(void* const* d_in, const int* in_sizes, int n_in,
                              void* d_out, int out_size)
{
    const float* x     = (const float*)d_in[0];
    const float* in_w  = (const float*)d_in[1];
    const float* in_b  = (const float*)d_in[2];
    const float* out_w = (const float*)d_in[3];
    const float* out_b = (const float*)d_in[4];
    const float* fc1_w = (const float*)d_in[5];
    const float* fc1_b = (const float*)d_in[6];
    const float* fc2_w = (const float*)d_in[7];
    const float* fc2_b = (const float*)d_in[8];
    const float* ln1_w = (const float*)d_in[9];
    const float* ln1_b = (const float*)d_in[10];
    const float* ln2_w = (const float*)d_in[11];
    const float* ln2_b = (const float*)d_in[12];
    const void*  pad   = d_in[13];
    // d_in[14] = attn_mask: deterministic causal triu(ones,1); applied analytically.
    float* out = (float*)d_out;

    float *p_qkv, *p_attn, *p_y1, *p_ffh;
    cudaGetSymbolAddress((void**)&p_qkv,  g_qkv);
    cudaGetSymbolAddress((void**)&p_attn, g_attn);
    cudaGetSymbolAddress((void**)&p_y1,   g_y1);
    cudaGetSymbolAddress((void**)&p_ffh,  g_ffh);

    probe_mask<<<1, 256>>>((const unsigned char*)pad);

    // 1. QKV projection
    gemm_nt<false, false><<<dim3(3 * EE / GT, MM / GT), 256>>>(
        x, in_w, in_b, nullptr, p_qkv, MM, 3 * EE, EE);

    // 2. attention
    attn_kernel<<<dim3(TT / 64, HH, BB), 64>>>(p_qkv, pad, p_attn);

    // 3. out projection + bias + residual(x)
    gemm_nt<false, true><<<dim3(EE / GT, MM / GT), 256>>>(
        p_attn, out_w, out_b, x, p_y1, MM, EE, EE);

    // 4. LN1 (in-place)
    ln_kernel<<<MM, 256>>>(p_y1, ln1_w, ln1_b);

    // 5. FC1 + ReLU
    gemm_nt<true, false><<<dim3(FFD / GT, MM / GT), 256>>>(
        p_y1, fc1_w, fc1_b, nullptr, p_ffh, MM, FFD, EE);

    // 6. FC2 + bias + residual(y1) -> d_out
    gemm_nt<false, true><<<dim3(EE / GT, MM / GT), 256>>>(
        p_ffh, fc2_w, fc2_b, p_y1, out, MM, EE, FFD);

    // 7. LN2 (in-place on d_out)
    ln_kernel<<<MM, 256>>>(out, ln2_w, ln2_b);
}

// round 8
// speedup vs baseline: 2.8790x; 2.8790x over previous
#include <cuda_runtime.h>
#include <cuda_bf16.h>
#include <cstdint>

#define BB 8
#define TT 1024
#define EE 1024
#define HH 16
#define HD 64
#define FFD 4096
#define MM (BB*TT)          // 8192 rows
#define SCALE 0.125f        // HD^-0.5

// ---------------- scratch (device globals: allocation-free) ----------------
static __device__ float g_qkv[MM * 3 * EE];   // 96 MB
static __device__ float g_attn[MM * EE];      // 32 MB
static __device__ float g_y1[MM * EE];        // 32 MB
static __device__ float g_ffh[MM * FFD];      // 128 MB
static __device__ int   g_mask_mode;          // 0=u8, 1=i32, 2=f32

// ================= PTX helpers (arch-neutral: sm_80+ mma path) =============
__device__ __forceinline__ uint32_t smem_u32(const void* p) {
    uint32_t a;
    asm("{ .reg .u64 t; cvta.to.shared.u64 t, %1; cvt.u32.u64 %0, t; }"
        : "=r"(a) : "l"(p));
    return a;
}

__device__ __forceinline__ void ldsm4(uint32_t* r, uint32_t addr) {
    asm volatile("ldmatrix.sync.aligned.m8n8.x4.shared.b16 {%0,%1,%2,%3}, [%4];"
                 : "=r"(r[0]), "=r"(r[1]), "=r"(r[2]), "=r"(r[3]) : "r"(addr));
}

__device__ __forceinline__ void mma16816(float* d, const uint32_t* a,
                                         uint32_t b0, uint32_t b1) {
    asm volatile(
        "mma.sync.aligned.m16n8k16.row.col.f32.bf16.bf16.f32 "
        "{%0,%1,%2,%3}, {%4,%5,%6,%7}, {%8,%9}, {%0,%1,%2,%3};"
        : "+f"(d[0]), "+f"(d[1]), "+f"(d[2]), "+f"(d[3])
        : "r"(a[0]), "r"(a[1]), "r"(a[2]), "r"(a[3]), "r"(b0), "r"(b1));
}

static __device__ __forceinline__ uint32_t bits2(__nv_bfloat162 v) {
    return *reinterpret_cast<uint32_t*>(&v);
}

// ---------------- mask dtype probe ----------------
__global__ void probe_mask(const unsigned char* __restrict__ p) {
    __shared__ int cnt[4];
    if (threadIdx.x < 4) cnt[threadIdx.x] = 0;
    __syncthreads();
    int local[4] = {0, 0, 0, 0};
    for (int i = threadIdx.x; i < 8192; i += blockDim.x)
        if (p[i]) local[i & 3]++;
    #pragma unroll
    for (int c = 0; c < 4; c++)
        if (local[c]) atomicAdd(&cnt[c], local[c]);
    __syncthreads();
    if (threadIdx.x == 0) {
        int c0 = cnt[0], c1 = cnt[1], c2 = cnt[2], c3 = cnt[3];
        int mode = 0;
        if (c0 > 0 && c1 == 0 && c2 == 0 && c3 == 0) mode = 1;        // int32
        else if (c0 == 0 && c1 == 0 && (c2 > 0 || c3 > 0)) mode = 2;  // float32
        g_mask_mode = mode;
    }
}

// =================================================================
// HMMA GEMM: C[M,N] = act(A[M,K] @ W[N,K]^T + bias (+R))
// fp32 in/out, bf16x3 compensated (hh + hl + lh), fp32 accumulate.
// 128x128 tile, BK=32, 8 warps (2x4 -> 64x32 warp tile), reg prefetch.
// =================================================================
#define LDSB 80                     // smem row stride in bytes (40 bf16, 16B pad)
#define TILEB (128 * LDSB)          // 10240 bytes per bf16 tile
#define SMEM_GEMM_TOTAL (4 * TILEB) // Ah | Al | Bh | Bl = 40960 bytes

template <bool RELU, bool RES>
__global__ __launch_bounds__(256) void gemm_mma(
    const float* __restrict__ A, const float* __restrict__ W,
    const float* __restrict__ bias, const float* __restrict__ R,
    float* __restrict__ C, int M, int N, int K)
{
    extern __shared__ char smem[];
    char* sAh = smem;
    char* sAl = smem + TILEB;
    char* sBh = smem + 2 * TILEB;
    char* sBl = smem + 3 * TILEB;
    const uint32_t uAh = smem_u32(sAh);
    const uint32_t uAl = uAh + TILEB;
    const uint32_t uBh = uAh + 2 * TILEB;
    const uint32_t uBl = uAh + 3 * TILEB;

    const int tid  = threadIdx.x;
    const int wid  = tid >> 5;
    const int lane = tid & 31;
    const int wm = wid & 1;          // 0..1  (64-row band)
    const int wn = wid >> 1;         // 0..3  (32-col band)
    const int m0 = blockIdx.y * 128;
    const int n0 = blockIdx.x * 128;

    // loader mapping: 4 float4 per thread per operand per chunk
    const int lrow = tid >> 3;       // base row (i-th f4: idx = i*256+tid)
    const int lc4  = tid & 7;        // float4 column index (8 per row of 32)

    float4 pa[4], pb[4];
    #define PRELOAD(ch) do { \
        _Pragma("unroll") \
        for (int i = 0; i < 4; i++) { \
            int idx = i * 256 + tid; \
            int row = idx >> 3, c4 = idx & 7; \
            pa[i] = *(const float4*)(A + (size_t)(m0 + row) * K + (ch) * 32 + c4 * 4); \
            pb[i] = *(const float4*)(W + (size_t)(n0 + row) * K + (ch) * 32 + c4 * 4); \
        } \
    } while (0)

    float acc[4][4][4];
    #pragma unroll
    for (int a = 0; a < 4; a++)
        #pragma unroll
        for (int b = 0; b < 4; b++)
            #pragma unroll
            for (int c = 0; c < 4; c++) acc[a][b][c] = 0.f;

    // ldmatrix per-lane address offsets
    const uint32_t a_off = (uint32_t)(wm * 64 + (lane & 15)) * LDSB + ((lane >> 4) << 4);
    const uint32_t b_off = (uint32_t)(wn * 32 + (lane & 15)) * LDSB + ((lane >> 4) << 4);

    const int nch = K >> 5;
    PRELOAD(0);

    for (int ch = 0; ch < nch; ch++) {
        // convert + store staged chunk to smem (hi/lo split)
        #pragma unroll
        for (int i = 0; i < 4; i++) {
            int idx = i * 256 + tid;
            int row = idx >> 3, c4 = idx & 7;
            uint32_t off = (uint32_t)row * LDSB + c4 * 8;
            {
                float4 v = pa[i];
                __nv_bfloat162 h01 = __float22bfloat162_rn(make_float2(v.x, v.y));
                __nv_bfloat162 h23 = __float22bfloat162_rn(make_float2(v.z, v.w));
                __nv_bfloat162 l01 = __float22bfloat162_rn(make_float2(
                    v.x - __low2float(h01), v.y - __high2float(h01)));
                __nv_bfloat162 l23 = __float22bfloat162_rn(make_float2(
                    v.z - __low2float(h23), v.w - __high2float(h23)));
                *(uint2*)(sAh + off) = make_uint2(bits2(h01), bits2(h23));
                *(uint2*)(sAl + off) = make_uint2(bits2(l01), bits2(l23));
            }
            {
                float4 v = pb[i];
                __nv_bfloat162 h01 = __float22bfloat162_rn(make_float2(v.x, v.y));
                __nv_bfloat162 h23 = __float22bfloat162_rn(make_float2(v.z, v.w));
                __nv_bfloat162 l01 = __float22bfloat162_rn(make_float2(
                    v.x - __low2float(h01), v.y - __high2float(h01)));
                __nv_bfloat162 l23 = __float22bfloat162_rn(make_float2(
                    v.z - __low2float(h23), v.w - __high2float(h23)));
                *(uint2*)(sBh + off) = make_uint2(bits2(h01), bits2(h23));
                *(uint2*)(sBl + off) = make_uint2(bits2(l01), bits2(l23));
            }
        }
        __syncthreads();

        if (ch + 1 < nch) PRELOAD(ch + 1);

        // 3 compensation passes: (Ah,Bh), (Ah,Bl), (Al,Bh)
        #pragma unroll
        for (int pass = 0; pass < 3; pass++) {
            const uint32_t uA = (pass == 2) ? uAl : uAh;
            const uint32_t uB = (pass == 1) ? uBl : uBh;
            #pragma unroll
            for (int kk = 0; kk < 2; kk++) {
                const uint32_t kb = kk * 32;   // 16 bf16 = 32 bytes
                uint32_t afr[4][4];
                #pragma unroll
                for (int mt = 0; mt < 4; mt++)
                    ldsm4(afr[mt], uA + a_off + mt * 16 * LDSB + kb);
                uint32_t bfr[2][4];
                #pragma unroll
                for (int g = 0; g < 2; g++)
                    ldsm4(bfr[g], uB + b_off + g * 16 * LDSB + kb);
                #pragma unroll
                for (int mt = 0; mt < 4; mt++) {
                    #pragma unroll
                    for (int g = 0; g < 2; g++) {
                        mma16816(acc[mt][2 * g],     afr[mt], bfr[g][0], bfr[g][2]);
                        mma16816(acc[mt][2 * g + 1], afr[mt], bfr[g][1], bfr[g][3]);
                    }
                }
            }
        }
        __syncthreads();
    }

    // ---------------- epilogue ----------------
    const int gr = lane >> 2;        // 0..7
    const int gc = (lane & 3) * 2;   // 0,2,4,6
    #pragma unroll
    for (int mt = 0; mt < 4; mt++) {
        const int mrow0 = m0 + wm * 64 + mt * 16 + gr;
        #pragma unroll
        for (int nt = 0; nt < 4; nt++) {
            const int ncol = n0 + wn * 32 + nt * 8 + gc;
            float2 bv = *(const float2*)(bias + ncol);
            #pragma unroll
            for (int half = 0; half < 2; half++) {
                const int m = mrow0 + half * 8;
                float2 o;
                o.x = acc[mt][nt][2 * half + 0] + bv.x;
                o.y = acc[mt][nt][2 * half + 1] + bv.y;
                if (RES) {
                    float2 rv = *(const float2*)(R + (size_t)m * N + ncol);
                    o.x += rv.x; o.y += rv.y;
                }
                if (RELU) {
                    o.x = fmaxf(o.x, 0.f);
                    o.y = fmaxf(o.y, 0.f);
                }
                *(float2*)(C + (size_t)m * N + ncol) = o;
            }
        }
    }
}

// ---------------- flash attention (fp32, causal + padding) ----------------
__global__ __launch_bounds__(64) void attn_kernel(
    const float* __restrict__ qkv, const void* __restrict__ pad,
    float* __restrict__ out)
{
    __shared__ float Ks[64 * 64];
    __shared__ float Vs[64 * 64];
    __shared__ unsigned char pmask[64];

    const int qt = blockIdx.x, h = blockIdx.y, b = blockIdx.z;
    const int tid = threadIdx.x;
    const int tq = qt * 64 + tid;
    const int row3 = 3 * EE;
    const int mode = g_mask_mode;

    const float* qrow = qkv + (size_t)(b * TT + tq) * row3 + h * HD;
    float q[HD];
    #pragma unroll
    for (int d = 0; d < HD; d++) q[d] = qrow[d] * SCALE;

    float o[HD];
    #pragma unroll
    for (int d = 0; d < HD; d++) o[d] = 0.f;
    float mrun = -INFINITY, lrun = 0.f;

    const int nkt = qt + 1;
    for (int kt = 0; kt < nkt; kt++) {
        const int t0 = kt * 64;
        const float* kbase = qkv + (size_t)(b * TT + t0) * row3 + EE + h * HD;
        const float* vbase = kbase + EE;
        #pragma unroll
        for (int r = 0; r < 16; r++) {
            int linear = r * 64 + tid;
            int j = linear >> 4;
            int d4 = (linear & 15) * 4;
            *(float4*)&Ks[j * 64 + d4] = *(const float4*)(kbase + (size_t)j * row3 + d4);
            *(float4*)&Vs[j * 64 + d4] = *(const float4*)(vbase + (size_t)j * row3 + d4);
        }
        {
            int tk = t0 + tid;
            unsigned char pm;
            if (mode == 1)      pm = (((const int*)pad)[b * TT + tk] != 0);
            else if (mode == 2) pm = (((const float*)pad)[b * TT + tk] != 0.f);
            else                pm = (((const unsigned char*)pad)[b * TT + tk] != 0);
            pmask[tid] = pm;
        }
        __syncthreads();

        float s[64];
        float tmax = -INFINITY;
        for (int j = 0; j < 64; j++) {
            int tk = t0 + j;
            if (tk <= tq && !pmask[j]) {
                float a0 = 0.f, a1 = 0.f;
                #pragma unroll
                for (int d4 = 0; d4 < HD; d4 += 8) {
                    float4 k0v = *(const float4*)&Ks[j * 64 + d4];
                    float4 k1v = *(const float4*)&Ks[j * 64 + d4 + 4];
                    a0 += q[d4 + 0] * k0v.x + q[d4 + 1] * k0v.y
                        + q[d4 + 2] * k0v.z + q[d4 + 3] * k0v.w;
                    a1 += q[d4 + 4] * k1v.x + q[d4 + 5] * k1v.y
                        + q[d4 + 6] * k1v.z + q[d4 + 7] * k1v.w;
                }
                float a = a0 + a1;
                s[j] = a;
                tmax = fmaxf(tmax, a);
            } else {
                s[j] = -INFINITY;
            }
        }

        if (tmax != -INFINITY) {
            float mnew = fmaxf(mrun, tmax);
            float alpha = __expf(mrun - mnew);
            lrun *= alpha;
            #pragma unroll
            for (int d = 0; d < HD; d++) o[d] *= alpha;
            for (int j = 0; j < 64; j++) {
                float p = __expf(s[j] - mnew);
                lrun += p;
                #pragma unroll
                for (int d4 = 0; d4 < HD; d4 += 4) {
                    float4 vv = *(const float4*)&Vs[j * 64 + d4];
                    o[d4 + 0] += p * vv.x; o[d4 + 1] += p * vv.y;
                    o[d4 + 2] += p * vv.z; o[d4 + 3] += p * vv.w;
                }
            }
            mrun = mnew;
        }
        __syncthreads();
    }

    const float inv = 1.f / lrun;
    float* orow = out + (size_t)(b * TT + tq) * EE + h * HD;
    #pragma unroll
    for (int d = 0; d < HD; d++) orow[d] = o[d] * inv;
}

// ---------------- LayerNorm in-place, one block per row ----------------
__global__ __launch_bounds__(256) void ln_kernel(
    float* __restrict__ X, const float* __restrict__ w,
    const float* __restrict__ bias)
{
    __shared__ float red[8];
    const int row = blockIdx.x, tid = threadIdx.x;
    float4* xr = (float4*)(X + (size_t)row * EE);
    float4 v = xr[tid];

    float s = v.x + v.y + v.z + v.w;
    #pragma unroll
    for (int o = 16; o; o >>= 1) s += __shfl_xor_sync(0xffffffffu, s, o);
    if ((tid & 31) == 0) red[tid >> 5] = s;
    __syncthreads();
    float tot = red[0] + red[1] + red[2] + red[3] + red[4] + red[5] + red[6] + red[7];
    const float mean = tot * (1.f / EE);

    float dx = v.x - mean, dy = v.y - mean, dz = v.z - mean, dw = v.w - mean;
    float s2 = dx * dx + dy * dy + dz * dz + dw * dw;
    __syncthreads();
    #pragma unroll
    for (int o = 16; o; o >>= 1) s2 += __shfl_xor_sync(0xffffffffu, s2, o);
    if ((tid & 31) == 0) red[tid >> 5] = s2;
    __syncthreads();
    float tot2 = red[0] + red[1] + red[2] + red[3] + red[4] + red[5] + red[6] + red[7];
    const float var = tot2 * (1.f / EE);
    const float inv = rsqrtf(var + 1e-12f);

    float4 wv = ((const float4*)w)[tid];
    float4 bv = ((const float4*)bias)[tid];
    float4 r;
    r.x = dx * inv * wv.x + bv.x;
    r.y = dy * inv * wv.y + bv.y;
    r.z = dz * inv * wv.z + bv.z;
    r.w = dw * inv * wv.w + bv.w;
    xr[tid] = r;
}

// ---------------- launch ----------------
extern "C" void kernel_launch(void* const* d_in, const int* in_sizes, int n_in,
                              void* d_out, int out_size)
{
    const float* x     = (const float*)d_in[0];
    const float* in_w  = (const float*)d_in[1];
    const float* in_b  = (const float*)d_in[2];
    const float* out_w = (const float*)d_in[3];
    const float* out_b = (const float*)d_in[4];
    const float* fc1_w = (const float*)d_in[5];
    const float* fc1_b = (const float*)d_in[6];
    const float* fc2_w = (const float*)d_in[7];
    const float* fc2_b = (const float*)d_in[8];
    const float* ln1_w = (const float*)d_in[9];
    const float* ln1_b = (const float*)d_in[10];
    const float* ln2_w = (const float*)d_in[11];
    const float* ln2_b = (const float*)d_in[12];
    const void*  pad   = d_in[13];
    float* out = (float*)d_out;

    float *p_qkv, *p_attn, *p_y1, *p_ffh;
    cudaGetSymbolAddress((void**)&p_qkv,  g_qkv);
    cudaGetSymbolAddress((void**)&p_attn, g_attn);
    cudaGetSymbolAddress((void**)&p_y1,   g_y1);
    cudaGetSymbolAddress((void**)&p_ffh,  g_ffh);

    probe_mask<<<1, 256>>>((const unsigned char*)pad);

    // 1. QKV projection
    gemm_mma<false, false><<<dim3(3 * EE / 128, MM / 128), 256, SMEM_GEMM_TOTAL>>>(
        x, in_w, in_b, nullptr, p_qkv, MM, 3 * EE, EE);

    // 2. attention
    attn_kernel<<<dim3(TT / 64, HH, BB), 64>>>(p_qkv, pad, p_attn);

    // 3. out projection + bias + residual(x)
    gemm_mma<false, true><<<dim3(EE / 128, MM / 128), 256, SMEM_GEMM_TOTAL>>>(
        p_attn, out_w, out_b, x, p_y1, MM, EE, EE);

    // 4. LN1 (in-place)
    ln_kernel<<<MM, 256>>>(p_y1, ln1_w, ln1_b);

    // 5. FC1 + ReLU
    gemm_mma<true, false><<<dim3(FFD / 128, MM / 128), 256, SMEM_GEMM_TOTAL>>>(
        p_y1, fc1_w, fc1_b, nullptr, p_ffh, MM, FFD, EE);

    // 6. FC2 + bias + residual(y1) -> d_out
    gemm_mma<false, true><<<dim3(EE / 128, MM / 128), 256, SMEM_GEMM_TOTAL>>>(
        p_ffh, fc2_w, fc2_b, p_y1, out, MM, EE, FFD);

    // 7. LN2 (in-place on d_out)
    ln_kernel<<<MM, 256>>>(out, ln2_w, ln2_b);
}

// round 9
// speedup vs baseline: 3.2619x; 1.1330x over previous
#include <cuda_runtime.h>
#include <cuda_bf16.h>
#include <cstdint>

#define BB 8
#define TT 1024
#define EE 1024
#define HH 16
#define HD 64
#define FFD 4096
#define MM (BB*TT)          // 8192 rows
#define SCALE 0.125f        // HD^-0.5

// ---------------- scratch (device globals: allocation-free) ----------------
static __device__ float g_qkv[MM * 3 * EE];   // 96 MB fp32
static __device__ float g_y1[MM * EE];        // 32 MB fp32 (LN1 out, FC2 residual)
static __device__ __nv_bfloat16 g_xh[MM * EE],  g_xl[MM * EE];    // x hi/lo
static __device__ __nv_bfloat16 g_ah[MM * EE],  g_al[MM * EE];    // attn out hi/lo
static __device__ __nv_bfloat16 g_y1h[MM * EE], g_y1l[MM * EE];   // LN1 out hi/lo
static __device__ __nv_bfloat16 g_fh[MM * FFD], g_fl[MM * FFD];   // FC1 out hi/lo
static __device__ __nv_bfloat16 g_wih[3*EE*EE], g_wil[3*EE*EE];
static __device__ __nv_bfloat16 g_woh[EE*EE],   g_wol[EE*EE];
static __device__ __nv_bfloat16 g_w1h[FFD*EE],  g_w1l[FFD*EE];
static __device__ __nv_bfloat16 g_w2h[EE*FFD],  g_w2l[EE*FFD];
static __device__ int g_mask_mode;            // 0=u8, 1=i32, 2=f32

// ================= PTX helpers =================
__device__ __forceinline__ uint32_t smem_u32(const void* p) {
    uint32_t a;
    asm("{ .reg .u64 t; cvta.to.shared.u64 t, %1; cvt.u32.u64 %0, t; }"
        : "=r"(a) : "l"(p));
    return a;
}
__device__ __forceinline__ void ldsm4(uint32_t* r, uint32_t addr) {
    asm volatile("ldmatrix.sync.aligned.m8n8.x4.shared.b16 {%0,%1,%2,%3}, [%4];"
                 : "=r"(r[0]), "=r"(r[1]), "=r"(r[2]), "=r"(r[3]) : "r"(addr));
}
__device__ __forceinline__ void mma16816(float* d, const uint32_t* a,
                                         uint32_t b0, uint32_t b1) {
    asm volatile(
        "mma.sync.aligned.m16n8k16.row.col.f32.bf16.bf16.f32 "
        "{%0,%1,%2,%3}, {%4,%5,%6,%7}, {%8,%9}, {%0,%1,%2,%3};"
        : "+f"(d[0]), "+f"(d[1]), "+f"(d[2]), "+f"(d[3])
        : "r"(a[0]), "r"(a[1]), "r"(a[2]), "r"(a[3]), "r"(b0), "r"(b1));
}
__device__ __forceinline__ void cpa16(uint32_t dst, const void* src) {
    asm volatile("cp.async.cg.shared.global [%0], [%1], 16;" :: "r"(dst), "l"(src));
}
__device__ __forceinline__ void cpa_commit() {
    asm volatile("cp.async.commit_group;" ::: "memory");
}
__device__ __forceinline__ void cpa_wait1() {
    asm volatile("cp.async.wait_group 1;" ::: "memory");
}

// ---------------- mask dtype probe ----------------
__global__ void probe_mask(const unsigned char* __restrict__ p) {
    __shared__ int cnt[4];
    if (threadIdx.x < 4) cnt[threadIdx.x] = 0;
    __syncthreads();
    int local[4] = {0, 0, 0, 0};
    for (int i = threadIdx.x; i < 8192; i += blockDim.x)
        if (p[i]) local[i & 3]++;
    #pragma unroll
    for (int c = 0; c < 4; c++)
        if (local[c]) atomicAdd(&cnt[c], local[c]);
    __syncthreads();
    if (threadIdx.x == 0) {
        int c0 = cnt[0], c1 = cnt[1], c2 = cnt[2], c3 = cnt[3];
        int mode = 0;
        if (c0 > 0 && c1 == 0 && c2 == 0 && c3 == 0) mode = 1;
        else if (c0 == 0 && c1 == 0 && (c2 > 0 || c3 > 0)) mode = 2;
        g_mask_mode = mode;
    }
}

// ---------------- fp32 -> bf16 hi/lo split ----------------
__global__ __launch_bounds__(256) void convert_hl(
    const float* __restrict__ in, __nv_bfloat16* __restrict__ h,
    __nv_bfloat16* __restrict__ l, int n4)
{
    int i = blockIdx.x * blockDim.x + threadIdx.x;
    if (i >= n4) return;
    float4 v = ((const float4*)in)[i];
    __nv_bfloat162 h01 = __float22bfloat162_rn(make_float2(v.x, v.y));
    __nv_bfloat162 h23 = __float22bfloat162_rn(make_float2(v.z, v.w));
    __nv_bfloat162 l01 = __float22bfloat162_rn(make_float2(
        v.x - __low2float(h01), v.y - __high2float(h01)));
    __nv_bfloat162 l23 = __float22bfloat162_rn(make_float2(
        v.z - __low2float(h23), v.w - __high2float(h23)));
    ((__nv_bfloat162*)h)[2*i]   = h01;
    ((__nv_bfloat162*)h)[2*i+1] = h23;
    ((__nv_bfloat162*)l)[2*i]   = l01;
    ((__nv_bfloat162*)l)[2*i+1] = l23;
}

// =================================================================
// Pure-bf16 HMMA GEMM: C = act(A @ W^T + bias (+R))
// A,W pre-split hi/lo bf16 [*,K] K-major. 128x128 CTA tile, 4 warps
// (64x64 warp tile), BK=32, 3-stage cp.async, swizzled 64B-row smem.
// =================================================================
#define STG_T 8192                 // bytes/tensor/stage (128 rows * 64B)
#define STG_ALL 32768              // 4 tensors
#define SMEMG (3 * STG_ALL)        // 96 KB

#define MMAS(AF, BF) do { \
    _Pragma("unroll") \
    for (int mt = 0; mt < 4; mt++) { \
        _Pragma("unroll") \
        for (int g = 0; g < 4; g++) { \
            mma16816(acc[mt][2*g],   AF[mt], BF[g][0], BF[g][2]); \
            mma16816(acc[mt][2*g+1], AF[mt], BF[g][1], BF[g][3]); \
        } \
    } \
} while (0)

#define LOAD_STAGE(stg, ch) do { \
    const uint32_t _base = sb + (stg) * STG_ALL + l_dst0; \
    const int _ko = (ch) * 32 + l_k; \
    _Pragma("unroll") \
    for (int i = 0; i < 16; i++) { \
        const int t = i >> 2; \
        const int rr = l_row + (i & 3) * 32; \
        const __nv_bfloat16* _s = \
            (t < 2 ? gA[t] : gW[t - 2]) + (size_t)rr * K + _ko; \
        cpa16(_base + t * STG_T + (i & 3) * 2048, _s); \
    } \
} while (0)

template <int RELU, int RES, int OUTHL>
__global__ __launch_bounds__(128) void gemm_hl(
    const __nv_bfloat16* __restrict__ Ah, const __nv_bfloat16* __restrict__ Al,
    const __nv_bfloat16* __restrict__ Wh, const __nv_bfloat16* __restrict__ Wl,
    const float* __restrict__ bias, const float* __restrict__ R,
    float* __restrict__ Cf, __nv_bfloat16* __restrict__ Ch,
    __nv_bfloat16* __restrict__ Cl, int M, int N, int K)
{
    extern __shared__ char smem[];
    const uint32_t sb = smem_u32(smem);
    const int tid = threadIdx.x, lane = tid & 31, wid = tid >> 5;
    const int wm = wid & 1, wn = wid >> 1;
    const int m0 = blockIdx.y * 128, n0 = blockIdx.x * 128;

    // loader constants: thread -> (row base, seg, swizzle) all static
    const uint32_t l_sw = (uint32_t)(((tid & 3) ^ ((tid >> 2) & 3) ^ ((tid >> 4) & 3)) << 4);
    const uint32_t l_dst0 = (uint32_t)((tid >> 2) << 6) + l_sw;
    const int l_row = tid >> 2;          // 0..31
    const int l_k   = (tid & 3) * 8;     // bf16 elems
    const __nv_bfloat16* gA[2] = {Ah + (size_t)m0 * K, Al + (size_t)m0 * K};
    const __nv_bfloat16* gW[2] = {Wh + (size_t)n0 * K, Wl + (size_t)n0 * K};

    // reader constants
    const int r15 = lane & 15;
    const int hs  = lane >> 4;
    const uint32_t xorc = (uint32_t)((r15 & 3) ^ ((r15 >> 2) & 3));
    const uint32_t aro = (uint32_t)(wm * 64 + r15) * 64;
    const uint32_t bro = (uint32_t)(wn * 64 + r15) * 64;

    float acc[4][8][4];
    #pragma unroll
    for (int a = 0; a < 4; a++)
        #pragma unroll
        for (int b = 0; b < 8; b++)
            #pragma unroll
            for (int c = 0; c < 4; c++) acc[a][b][c] = 0.f;

    const int nch = K >> 5;

    LOAD_STAGE(0, 0); cpa_commit();
    LOAD_STAGE(1, 1); cpa_commit();

    int stg = 0;
    for (int ch = 0; ch < nch; ch++) {
        cpa_wait1();
        __syncthreads();
        const int nc = ch + 2;
        if (nc < nch) {
            const int ns = (stg == 0) ? 2 : stg - 1;
            LOAD_STAGE(ns, nc);
        }
        cpa_commit();

        const uint32_t st = sb + stg * STG_ALL;
        #pragma unroll
        for (int kk = 0; kk < 2; kk++) {
            const uint32_t ksw = (((uint32_t)(2 * kk + hs)) ^ xorc) << 4;
            uint32_t af[4][4], bf[4][4], cf2[4][4];
            #pragma unroll
            for (int mt = 0; mt < 4; mt++)
                ldsm4(af[mt], st + 0 * STG_T + aro + mt * 1024 + ksw);
            #pragma unroll
            for (int g = 0; g < 4; g++)
                ldsm4(bf[g], st + 2 * STG_T + bro + g * 1024 + ksw);
            MMAS(af, bf);                       // hi * hi
            #pragma unroll
            for (int g = 0; g < 4; g++)
                ldsm4(cf2[g], st + 3 * STG_T + bro + g * 1024 + ksw);
            MMAS(af, cf2);                      // hi * lo
            #pragma unroll
            for (int mt = 0; mt < 4; mt++)
                ldsm4(af[mt], st + 1 * STG_T + aro + mt * 1024 + ksw);
            MMAS(af, bf);                       // lo * hi
        }
        stg = (stg == 2) ? 0 : stg + 1;
    }

    // ---------------- epilogue ----------------
    const int gr = lane >> 2;
    const int gc = (lane & 3) * 2;
    #pragma unroll
    for (int mt = 0; mt < 4; mt++) {
        #pragma unroll
        for (int half = 0; half < 2; half++) {
            const int m = m0 + wm * 64 + mt * 16 + gr + half * 8;
            #pragma unroll
            for (int nt = 0; nt < 8; nt++) {
                const int col = n0 + wn * 64 + nt * 8 + gc;
                float2 bv = *(const float2*)(bias + col);
                float ox = acc[mt][nt][2*half + 0] + bv.x;
                float oy = acc[mt][nt][2*half + 1] + bv.y;
                if (RES) {
                    float2 rv = *(const float2*)(R + (size_t)m * N + col);
                    ox += rv.x; oy += rv.y;
                }
                if (RELU) { ox = fmaxf(ox, 0.f); oy = fmaxf(oy, 0.f); }
                if (OUTHL) {
                    __nv_bfloat162 hp = __float22bfloat162_rn(make_float2(ox, oy));
                    __nv_bfloat162 lp = __float22bfloat162_rn(make_float2(
                        ox - __low2float(hp), oy - __high2float(hp)));
                    *(__nv_bfloat162*)(Ch + (size_t)m * N + col) = hp;
                    *(__nv_bfloat162*)(Cl + (size_t)m * N + col) = lp;
                } else {
                    *(float2*)(Cf + (size_t)m * N + col) = make_float2(ox, oy);
                }
            }
        }
    }
}

// ---------------- flash attention (fp32, causal + padding) ----------------
// writes bf16 hi/lo for the out-projection GEMM
__global__ __launch_bounds__(64) void attn_kernel(
    const float* __restrict__ qkv, const void* __restrict__ pad,
    __nv_bfloat16* __restrict__ outh, __nv_bfloat16* __restrict__ outl)
{
    __shared__ float Ks[64 * 64];
    __shared__ float Vs[64 * 64];
    __shared__ unsigned char pmask[64];

    const int qt = blockIdx.x, h = blockIdx.y, b = blockIdx.z;
    const int tid = threadIdx.x;
    const int tq = qt * 64 + tid;
    const int row3 = 3 * EE;
    const int mode = g_mask_mode;

    const float* qrow = qkv + (size_t)(b * TT + tq) * row3 + h * HD;
    float q[HD];
    #pragma unroll
    for (int d = 0; d < HD; d++) q[d] = qrow[d] * SCALE;

    float o[HD];
    #pragma unroll
    for (int d = 0; d < HD; d++) o[d] = 0.f;
    float mrun = -INFINITY, lrun = 0.f;

    const int nkt = qt + 1;
    for (int kt = 0; kt < nkt; kt++) {
        const int t0 = kt * 64;
        const float* kbase = qkv + (size_t)(b * TT + t0) * row3 + EE + h * HD;
        const float* vbase = kbase + EE;
        #pragma unroll
        for (int r = 0; r < 16; r++) {
            int linear = r * 64 + tid;
            int j = linear >> 4;
            int d4 = (linear & 15) * 4;
            *(float4*)&Ks[j * 64 + d4] = *(const float4*)(kbase + (size_t)j * row3 + d4);
            *(float4*)&Vs[j * 64 + d4] = *(const float4*)(vbase + (size_t)j * row3 + d4);
        }
        {
            int tk = t0 + tid;
            unsigned char pm;
            if (mode == 1)      pm = (((const int*)pad)[b * TT + tk] != 0);
            else if (mode == 2) pm = (((const float*)pad)[b * TT + tk] != 0.f);
            else                pm = (((const unsigned char*)pad)[b * TT + tk] != 0);
            pmask[tid] = pm;
        }
        __syncthreads();

        float s[64];
        float tmax = -INFINITY;
        for (int j = 0; j < 64; j++) {
            int tk = t0 + j;
            if (tk <= tq && !pmask[j]) {
                float a0 = 0.f, a1 = 0.f;
                #pragma unroll
                for (int d4 = 0; d4 < HD; d4 += 8) {
                    float4 k0v = *(const float4*)&Ks[j * 64 + d4];
                    float4 k1v = *(const float4*)&Ks[j * 64 + d4 + 4];
                    a0 += q[d4 + 0] * k0v.x + q[d4 + 1] * k0v.y
                        + q[d4 + 2] * k0v.z + q[d4 + 3] * k0v.w;
                    a1 += q[d4 + 4] * k1v.x + q[d4 + 5] * k1v.y
                        + q[d4 + 6] * k1v.z + q[d4 + 7] * k1v.w;
                }
                float a = a0 + a1;
                s[j] = a;
                tmax = fmaxf(tmax, a);
            } else {
                s[j] = -INFINITY;
            }
        }

        if (tmax != -INFINITY) {
            float mnew = fmaxf(mrun, tmax);
            float alpha = __expf(mrun - mnew);
            lrun *= alpha;
            #pragma unroll
            for (int d = 0; d < HD; d++) o[d] *= alpha;
            for (int j = 0; j < 64; j++) {
                float p = __expf(s[j] - mnew);
                lrun += p;
                #pragma unroll
                for (int d4 = 0; d4 < HD; d4 += 4) {
                    float4 vv = *(const float4*)&Vs[j * 64 + d4];
                    o[d4 + 0] += p * vv.x; o[d4 + 1] += p * vv.y;
                    o[d4 + 2] += p * vv.z; o[d4 + 3] += p * vv.w;
                }
            }
            mrun = mnew;
        }
        __syncthreads();
    }

    const float inv = 1.f / lrun;
    const size_t base = (size_t)(b * TT + tq) * EE + h * HD;
    #pragma unroll
    for (int d = 0; d < HD; d += 2) {
        float vx = o[d] * inv, vy = o[d + 1] * inv;
        __nv_bfloat162 hp = __float22bfloat162_rn(make_float2(vx, vy));
        __nv_bfloat162 lp = __float22bfloat162_rn(make_float2(
            vx - __low2float(hp), vy - __high2float(hp)));
        *(__nv_bfloat162*)(outh + base + d) = hp;
        *(__nv_bfloat162*)(outl + base + d) = lp;
    }
}

// ---------------- LayerNorm in-place (+ optional hi/lo emit) ----------------
template <int HL>
__global__ __launch_bounds__(256) void ln_kernel(
    float* __restrict__ X, const float* __restrict__ w,
    const float* __restrict__ bias,
    __nv_bfloat16* __restrict__ Yh, __nv_bfloat16* __restrict__ Yl)
{
    __shared__ float red[8];
    const int row = blockIdx.x, tid = threadIdx.x;
    float4* xr = (float4*)(X + (size_t)row * EE);
    float4 v = xr[tid];

    float s = v.x + v.y + v.z + v.w;
    #pragma unroll
    for (int o = 16; o; o >>= 1) s += __shfl_xor_sync(0xffffffffu, s, o);
    if ((tid & 31) == 0) red[tid >> 5] = s;
    __syncthreads();
    float tot = red[0] + red[1] + red[2] + red[3] + red[4] + red[5] + red[6] + red[7];
    const float mean = tot * (1.f / EE);

    float dx = v.x - mean, dy = v.y - mean, dz = v.z - mean, dw = v.w - mean;
    float s2 = dx * dx + dy * dy + dz * dz + dw * dw;
    __syncthreads();
    #pragma unroll
    for (int o = 16; o; o >>= 1) s2 += __shfl_xor_sync(0xffffffffu, s2, o);
    if ((tid & 31) == 0) red[tid >> 5] = s2;
    __syncthreads();
    float tot2 = red[0] + red[1] + red[2] + red[3] + red[4] + red[5] + red[6] + red[7];
    const float var = tot2 * (1.f / EE);
    const float inv = rsqrtf(var + 1e-12f);

    float4 wv = ((const float4*)w)[tid];
    float4 bv = ((const float4*)bias)[tid];
    float4 r;
    r.x = dx * inv * wv.x + bv.x;
    r.y = dy * inv * wv.y + bv.y;
    r.z = dz * inv * wv.z + bv.z;
    r.w = dw * inv * wv.w + bv.w;
    xr[tid] = r;
    if (HL) {
        const size_t base = (size_t)row * EE + tid * 4;
        __nv_bfloat162 h01 = __float22bfloat162_rn(make_float2(r.x, r.y));
        __nv_bfloat162 h23 = __float22bfloat162_rn(make_float2(r.z, r.w));
        __nv_bfloat162 l01 = __float22bfloat162_rn(make_float2(
            r.x - __low2float(h01), r.y - __high2float(h01)));
        __nv_bfloat162 l23 = __float22bfloat162_rn(make_float2(
            r.z - __low2float(h23), r.w - __high2float(h23)));
        *(__nv_bfloat162*)(Yh + base)     = h01;
        *(__nv_bfloat162*)(Yh + base + 2) = h23;
        *(__nv_bfloat162*)(Yl + base)     = l01;
        *(__nv_bfloat162*)(Yl + base + 2) = l23;
    }
}

// ---------------- launch ----------------
extern "C" void kernel_launch(void* const* d_in, const int* in_sizes, int n_in,
                              void* d_out, int out_size)
{
    const float* x     = (const float*)d_in[0];
    const float* in_w  = (const float*)d_in[1];
    const float* in_b  = (const float*)d_in[2];
    const float* out_w = (const float*)d_in[3];
    const float* out_b = (const float*)d_in[4];
    const float* fc1_w = (const float*)d_in[5];
    const float* fc1_b = (const float*)d_in[6];
    const float* fc2_w = (const float*)d_in[7];
    const float* fc2_b = (const float*)d_in[8];
    const float* ln1_w = (const float*)d_in[9];
    const float* ln1_b = (const float*)d_in[10];
    const float* ln2_w = (const float*)d_in[11];
    const float* ln2_b = (const float*)d_in[12];
    const void*  pad   = d_in[13];
    float* out = (float*)d_out;

    float *p_qkv, *p_y1;
    __nv_bfloat16 *p_xh, *p_xl, *p_ah, *p_al, *p_y1h, *p_y1l, *p_fh, *p_fl;
    __nv_bfloat16 *p_wih, *p_wil, *p_woh, *p_wol, *p_w1h, *p_w1l, *p_w2h, *p_w2l;
    cudaGetSymbolAddress((void**)&p_qkv, g_qkv);
    cudaGetSymbolAddress((void**)&p_y1,  g_y1);
    cudaGetSymbolAddress((void**)&p_xh,  g_xh);  cudaGetSymbolAddress((void**)&p_xl,  g_xl);
    cudaGetSymbolAddress((void**)&p_ah,  g_ah);  cudaGetSymbolAddress((void**)&p_al,  g_al);
    cudaGetSymbolAddress((void**)&p_y1h, g_y1h); cudaGetSymbolAddress((void**)&p_y1l, g_y1l);
    cudaGetSymbolAddress((void**)&p_fh,  g_fh);  cudaGetSymbolAddress((void**)&p_fl,  g_fl);
    cudaGetSymbolAddress((void**)&p_wih, g_wih); cudaGetSymbolAddress((void**)&p_wil, g_wil);
    cudaGetSymbolAddress((void**)&p_woh, g_woh); cudaGetSymbolAddress((void**)&p_wol, g_wol);
    cudaGetSymbolAddress((void**)&p_w1h, g_w1h); cudaGetSymbolAddress((void**)&p_w1l, g_w1l);
    cudaGetSymbolAddress((void**)&p_w2h, g_w2h); cudaGetSymbolAddress((void**)&p_w2l, g_w2l);

    cudaFuncSetAttribute(gemm_hl<0,0,0>, cudaFuncAttributeMaxDynamicSharedMemorySize, SMEMG);
    cudaFuncSetAttribute(gemm_hl<0,1,0>, cudaFuncAttributeMaxDynamicSharedMemorySize, SMEMG);
    cudaFuncSetAttribute(gemm_hl<1,0,1>, cudaFuncAttributeMaxDynamicSharedMemorySize, SMEMG);

    probe_mask<<<1, 256>>>((const unsigned char*)pad);

    // hi/lo splits: input x + the four weights
    convert_hl<<<(MM * EE / 4 + 255) / 256, 256>>>(x, p_xh, p_xl, MM * EE / 4);
    convert_hl<<<(3 * EE * EE / 4 + 255) / 256, 256>>>(in_w,  p_wih, p_wil, 3 * EE * EE / 4);
    convert_hl<<<(EE * EE / 4 + 255) / 256, 256>>>(out_w, p_woh, p_wol, EE * EE / 4);
    convert_hl<<<(FFD * EE / 4 + 255) / 256, 256>>>(fc1_w, p_w1h, p_w1l, FFD * EE / 4);
    convert_hl<<<(EE * FFD / 4 + 255) / 256, 256>>>(fc2_w, p_w2h, p_w2l, EE * FFD / 4);

    // 1. QKV projection -> fp32
    gemm_hl<0,0,0><<<dim3(3 * EE / 128, MM / 128), 128, SMEMG>>>(
        p_xh, p_xl, p_wih, p_wil, in_b, nullptr,
        p_qkv, nullptr, nullptr, MM, 3 * EE, EE);

    // 2. attention -> hi/lo
    attn_kernel<<<dim3(TT / 64, HH, BB), 64>>>(p_qkv, pad, p_ah, p_al);

    // 3. out projection + bias + residual(x) -> fp32 y1
    gemm_hl<0,1,0><<<dim3(EE / 128, MM / 128), 128, SMEMG>>>(
        p_ah, p_al, p_woh, p_wol, out_b, x,
        p_y1, nullptr, nullptr, MM, EE, EE);

    // 4. LN1 in-place + hi/lo emit
    ln_kernel<1><<<MM, 256>>>(p_y1, ln1_w, ln1_b, p_y1h, p_y1l);

    // 5. FC1 + ReLU -> hi/lo only
    gemm_hl<1,0,1><<<dim3(FFD / 128, MM / 128), 128, SMEMG>>>(
        p_y1h, p_y1l, p_w1h, p_w1l, fc1_b, nullptr,
        nullptr, p_fh, p_fl, MM, FFD, EE);

    // 6. FC2 + bias + residual(y1) -> d_out fp32
    gemm_hl<0,1,0><<<dim3(EE / 128, MM / 128), 128, SMEMG>>>(
        p_fh, p_fl, p_w2h, p_w2l, fc2_b, p_y1,
        out, nullptr, nullptr, MM, EE, FFD);

    // 7. LN2 in-place on d_out
    ln_kernel<0><<<MM, 256>>>(out, ln2_w, ln2_b, nullptr, nullptr);
}

// round 11
// speedup vs baseline: 4.5323x; 1.3895x over previous
#include <cuda_runtime.h>
#include <cuda_bf16.h>
#include <cstdint>

#define BB 8
#define TT 1024
#define EE 1024
#define HH 16
#define HD 64
#define FFD 4096
#define MM (BB*TT)          // 8192 rows
#define SCALE 0.125f        // HD^-0.5

// ---------------- scratch (device globals: allocation-free) ----------------
static __device__ float g_y1[MM * EE];        // fp32 (LN1 out, FC2 residual)
static __device__ __nv_bfloat16 g_qh[MM * 3 * EE], g_ql[MM * 3 * EE]; // qkv hi/lo
static __device__ __nv_bfloat16 g_xh[MM * EE],  g_xl[MM * EE];    // x hi/lo
static __device__ __nv_bfloat16 g_ah[MM * EE],  g_al[MM * EE];    // attn out hi/lo
static __device__ __nv_bfloat16 g_y1h[MM * EE], g_y1l[MM * EE];   // LN1 out hi/lo
static __device__ __nv_bfloat16 g_fh[MM * FFD], g_fl[MM * FFD];   // FC1 out hi/lo
static __device__ __nv_bfloat16 g_wih[3*EE*EE], g_wil[3*EE*EE];
static __device__ __nv_bfloat16 g_woh[EE*EE],   g_wol[EE*EE];
static __device__ __nv_bfloat16 g_w1h[FFD*EE],  g_w1l[FFD*EE];
static __device__ __nv_bfloat16 g_w2h[EE*FFD],  g_w2l[EE*FFD];
static __device__ int g_mask_mode;            // 0=u8, 1=i32, 2=f32

// ================= PTX helpers =================
__device__ __forceinline__ uint32_t smem_u32(const void* p) {
    uint32_t a;
    asm("{ .reg .u64 t; cvta.to.shared.u64 t, %1; cvt.u32.u64 %0, t; }"
        : "=r"(a) : "l"(p));
    return a;
}
__device__ __forceinline__ void ldsm4(uint32_t* r, uint32_t addr) {
    asm volatile("ldmatrix.sync.aligned.m8n8.x4.shared.b16 {%0,%1,%2,%3}, [%4];"
                 : "=r"(r[0]), "=r"(r[1]), "=r"(r[2]), "=r"(r[3]) : "r"(addr));
}
__device__ __forceinline__ void ldsm4t(uint32_t* r, uint32_t addr) {
    asm volatile("ldmatrix.sync.aligned.m8n8.x4.trans.shared.b16 {%0,%1,%2,%3}, [%4];"
                 : "=r"(r[0]), "=r"(r[1]), "=r"(r[2]), "=r"(r[3]) : "r"(addr));
}
__device__ __forceinline__ void mma16816(float* d, const uint32_t* a,
                                         uint32_t b0, uint32_t b1) {
    asm volatile(
        "mma.sync.aligned.m16n8k16.row.col.f32.bf16.bf16.f32 "
        "{%0,%1,%2,%3}, {%4,%5,%6,%7}, {%8,%9}, {%0,%1,%2,%3};"
        : "+f"(d[0]), "+f"(d[1]), "+f"(d[2]), "+f"(d[3])
        : "r"(a[0]), "r"(a[1]), "r"(a[2]), "r"(a[3]), "r"(b0), "r"(b1));
}
__device__ __forceinline__ void cpa16(uint32_t dst, const void* src) {
    asm volatile("cp.async.cg.shared.global [%0], [%1], 16;" :: "r"(dst), "l"(src));
}
__device__ __forceinline__ void cpa_commit() {
    asm volatile("cp.async.commit_group;" ::: "memory");
}
__device__ __forceinline__ void cpa_wait1() {
    asm volatile("cp.async.wait_group 1;" ::: "memory");
}
__device__ __forceinline__ void cpa_wait0() {
    asm volatile("cp.async.wait_group 0;" ::: "memory");
}
__device__ __forceinline__ float ex2f(float x) {
    float y;
    asm("ex2.approx.ftz.f32 %0, %1;" : "=f"(y) : "f"(x));
    return y;
}
__device__ __forceinline__ uint32_t packbf(float x, float y) {
    __nv_bfloat162 v = __float22bfloat162_rn(make_float2(x, y));
    return *reinterpret_cast<uint32_t*>(&v);
}

// ---------------- mask dtype probe ----------------
__global__ void probe_mask(const unsigned char* __restrict__ p) {
    __shared__ int cnt[4];
    if (threadIdx.x < 4) cnt[threadIdx.x] = 0;
    __syncthreads();
    int local[4] = {0, 0, 0, 0};
    for (int i = threadIdx.x; i < 8192; i += blockDim.x)
        if (p[i]) local[i & 3]++;
    #pragma unroll
    for (int c = 0; c < 4; c++)
        if (local[c]) atomicAdd(&cnt[c], local[c]);
    __syncthreads();
    if (threadIdx.x == 0) {
        int c0 = cnt[0], c1 = cnt[1], c2 = cnt[2], c3 = cnt[3];
        int mode = 0;
        if (c0 > 0 && c1 == 0 && c2 == 0 && c3 == 0) mode = 1;
        else if (c0 == 0 && c1 == 0 && (c2 > 0 || c3 > 0)) mode = 2;
        g_mask_mode = mode;
    }
}

// ---------------- fp32 -> bf16 hi/lo split ----------------
__global__ __launch_bounds__(256) void convert_hl(
    const float* __restrict__ in, __nv_bfloat16* __restrict__ h,
    __nv_bfloat16* __restrict__ l, int n4)
{
    int i = blockIdx.x * blockDim.x + threadIdx.x;
    if (i >= n4) return;
    float4 v = ((const float4*)in)[i];
    __nv_bfloat162 h01 = __float22bfloat162_rn(make_float2(v.x, v.y));
    __nv_bfloat162 h23 = __float22bfloat162_rn(make_float2(v.z, v.w));
    __nv_bfloat162 l01 = __float22bfloat162_rn(make_float2(
        v.x - __low2float(h01), v.y - __high2float(h01)));
    __nv_bfloat162 l23 = __float22bfloat162_rn(make_float2(
        v.z - __low2float(h23), v.w - __high2float(h23)));
    ((__nv_bfloat162*)h)[2*i]   = h01;
    ((__nv_bfloat162*)h)[2*i+1] = h23;
    ((__nv_bfloat162*)l)[2*i]   = l01;
    ((__nv_bfloat162*)l)[2*i+1] = l23;
}

// =================================================================
// Pure-bf16 HMMA GEMM: C = act(A @ W^T + bias (+R))
// =================================================================
#define STG_T 8192
#define STG_ALL 32768
#define SMEMG (3 * STG_ALL)

#define MMAS(AF, BF) do { \
    _Pragma("unroll") \
    for (int mt = 0; mt < 4; mt++) { \
        _Pragma("unroll") \
        for (int g = 0; g < 4; g++) { \
            mma16816(acc[mt][2*g],   AF[mt], BF[g][0], BF[g][2]); \
            mma16816(acc[mt][2*g+1], AF[mt], BF[g][1], BF[g][3]); \
        } \
    } \
} while (0)

#define LOAD_STAGE(stg, ch) do { \
    const uint32_t _base = sb + (stg) * STG_ALL + l_dst0; \
    const int _ko = (ch) * 32 + l_k; \
    _Pragma("unroll") \
    for (int i = 0; i < 16; i++) { \
        const int t = i >> 2; \
        const int rr = l_row + (i & 3) * 32; \
        const __nv_bfloat16* _s = \
            (t < 2 ? gA[t] : gW[t - 2]) + (size_t)rr * K + _ko; \
        cpa16(_base + t * STG_T + (i & 3) * 2048, _s); \
    } \
} while (0)

template <int RELU, int RES, int OUTHL>
__global__ __launch_bounds__(128) void gemm_hl(
    const __nv_bfloat16* __restrict__ Ah, const __nv_bfloat16* __restrict__ Al,
    const __nv_bfloat16* __restrict__ Wh, const __nv_bfloat16* __restrict__ Wl,
    const float* __restrict__ bias, const float* __restrict__ R,
    float* __restrict__ Cf, __nv_bfloat16* __restrict__ Ch,
    __nv_bfloat16* __restrict__ Cl, int M, int N, int K)
{
    extern __shared__ char smem[];
    const uint32_t sb = smem_u32(smem);
    const int tid = threadIdx.x, lane = tid & 31, wid = tid >> 5;
    const int wm = wid & 1, wn = wid >> 1;
    const int m0 = blockIdx.y * 128, n0 = blockIdx.x * 128;

    const uint32_t l_sw = (uint32_t)(((tid & 3) ^ ((tid >> 2) & 3) ^ ((tid >> 4) & 3)) << 4);
    const uint32_t l_dst0 = (uint32_t)((tid >> 2) << 6) + l_sw;
    const int l_row = tid >> 2;
    const int l_k   = (tid & 3) * 8;
    const __nv_bfloat16* gA[2] = {Ah + (size_t)m0 * K, Al + (size_t)m0 * K};
    const __nv_bfloat16* gW[2] = {Wh + (size_t)n0 * K, Wl + (size_t)n0 * K};

    const int r15 = lane & 15;
    const int hs  = lane >> 4;
    const uint32_t xorc = (uint32_t)((r15 & 3) ^ ((r15 >> 2) & 3));
    const uint32_t aro = (uint32_t)(wm * 64 + r15) * 64;
    const uint32_t bro = (uint32_t)(wn * 64 + r15) * 64;

    float acc[4][8][4];
    #pragma unroll
    for (int a = 0; a < 4; a++)
        #pragma unroll
        for (int b = 0; b < 8; b++)
            #pragma unroll
            for (int c = 0; c < 4; c++) acc[a][b][c] = 0.f;

    const int nch = K >> 5;

    LOAD_STAGE(0, 0); cpa_commit();
    LOAD_STAGE(1, 1); cpa_commit();

    int stg = 0;
    for (int ch = 0; ch < nch; ch++) {
        cpa_wait1();
        __syncthreads();
        const int nc = ch + 2;
        if (nc < nch) {
            const int ns = (stg == 0) ? 2 : stg - 1;
            LOAD_STAGE(ns, nc);
        }
        cpa_commit();

        const uint32_t st = sb + stg * STG_ALL;
        #pragma unroll
        for (int kk = 0; kk < 2; kk++) {
            const uint32_t ksw = (((uint32_t)(2 * kk + hs)) ^ xorc) << 4;
            uint32_t af[4][4], bf[4][4], cf2[4][4];
            #pragma unroll
            for (int mt = 0; mt < 4; mt++)
                ldsm4(af[mt], st + 0 * STG_T + aro + mt * 1024 + ksw);
            #pragma unroll
            for (int g = 0; g < 4; g++)
                ldsm4(bf[g], st + 2 * STG_T + bro + g * 1024 + ksw);
            MMAS(af, bf);
            #pragma unroll
            for (int g = 0; g < 4; g++)
                ldsm4(cf2[g], st + 3 * STG_T + bro + g * 1024 + ksw);
            MMAS(af, cf2);
            #pragma unroll
            for (int mt = 0; mt < 4; mt++)
                ldsm4(af[mt], st + 1 * STG_T + aro + mt * 1024 + ksw);
            MMAS(af, bf);
        }
        stg = (stg == 2) ? 0 : stg + 1;
    }

    const int gr = lane >> 2;
    const int gc = (lane & 3) * 2;
    #pragma unroll
    for (int mt = 0; mt < 4; mt++) {
        #pragma unroll
        for (int half = 0; half < 2; half++) {
            const int m = m0 + wm * 64 + mt * 16 + gr + half * 8;
            #pragma unroll
            for (int nt = 0; nt < 8; nt++) {
                const int col = n0 + wn * 64 + nt * 8 + gc;
                float2 bv = *(const float2*)(bias + col);
                float ox = acc[mt][nt][2*half + 0] + bv.x;
                float oy = acc[mt][nt][2*half + 1] + bv.y;
                if (RES) {
                    float2 rv = *(const float2*)(R + (size_t)m * N + col);
                    ox += rv.x; oy += rv.y;
                }
                if (RELU) { ox = fmaxf(ox, 0.f); oy = fmaxf(oy, 0.f); }
                if (OUTHL) {
                    __nv_bfloat162 hp = __float22bfloat162_rn(make_float2(ox, oy));
                    __nv_bfloat162 lp = __float22bfloat162_rn(make_float2(
                        ox - __low2float(hp), oy - __high2float(hp)));
                    *(__nv_bfloat162*)(Ch + (size_t)m * N + col) = hp;
                    *(__nv_bfloat162*)(Cl + (size_t)m * N + col) = lp;
                } else {
                    *(float2*)(Cf + (size_t)m * N + col) = make_float2(ox, oy);
                }
            }
        }
    }
}

// =================================================================
// Tensor-core flash attention.
// 128 threads (4 warps), 64 queries/block, grid (16, 16, 8).
// S = QK^T via bf16x3 HMMA; softmax base-2; PV via P hi/lo x V hi/lo.
// smem: Qh Ql Kh Kl Vh Vl (8 KB each, swizzled) + float bias[64].
// =================================================================
#define AQH 0
#define AQL 8192
#define AKH 16384
#define AKL 24576
#define AVH 32768
#define AVL 40960
#define ABIAS 49152
#define ATT_SMEM (49152 + 256)

__global__ __launch_bounds__(128) void attn_mma(
    const __nv_bfloat16* __restrict__ qkvh,
    const __nv_bfloat16* __restrict__ qkvl,
    const void* __restrict__ pad,
    __nv_bfloat16* __restrict__ outh, __nv_bfloat16* __restrict__ outl)
{
    extern __shared__ char sm[];
    const uint32_t sb = smem_u32(sm);
    float* sbias = (float*)(sm + ABIAS);

    const int tid = threadIdx.x, lane = tid & 31, w = tid >> 5;
    const int qt = blockIdx.x, h = blockIdx.y, b = blockIdx.z;
    const int q0 = qt * 64;
    const int row3 = 3 * EE;
    const int mode = g_mask_mode;
    const int gr = lane >> 2;
    const int r15 = lane & 15;
    const int hs = lane >> 4;

    // ---- stage Q (hi/lo) ----
    #pragma unroll
    for (int i = 0; i < 8; i++) {
        const int idx = i * 128 + tid;          // 0..1023
        const int t = idx >> 9;                  // 0=h 1=l
        const int c = idx & 511;
        const int row = c >> 3, g = c & 7;
        const __nv_bfloat16* src = (t ? qkvl : qkvh)
            + (size_t)(b * TT + q0 + row) * row3 + h * HD + g * 8;
        cpa16(sb + t * 8192 + row * 128 + (((uint32_t)(g ^ (row & 7))) << 4), src);
    }
    cpa_commit(); cpa_wait0();
    __syncthreads();

    // Q fragments -> registers (reused every k-tile)
    uint32_t qhf[4][4], qlf[4][4];
    #pragma unroll
    for (int kc = 0; kc < 4; kc++) {
        const int row = 16 * w + r15;
        const uint32_t a = (uint32_t)row * 128
            + (((uint32_t)((2 * kc + hs) ^ (row & 7))) << 4);
        ldsm4(qhf[kc], sb + AQH + a);
        ldsm4(qlf[kc], sb + AQL + a);
    }

    float m2[2] = {-1e30f, -1e30f};
    float lsum[2] = {0.f, 0.f};
    float o[8][4];
    #pragma unroll
    for (int nt = 0; nt < 8; nt++)
        #pragma unroll
        for (int i = 0; i < 4; i++) o[nt][i] = 0.f;

    const float cst = SCALE * 1.44269504f;   // scale * log2(e)

    for (int kt = 0; kt <= qt; kt++) {
        const int t0 = kt * 64;
        __syncthreads();   // all warps done reading previous tile's smem
        // stage K/V hi/lo
        #pragma unroll
        for (int i = 0; i < 16; i++) {
            const int idx = i * 128 + tid;       // 0..2047
            const int t4 = idx >> 9;             // 0 Kh, 1 Kl, 2 Vh, 3 Vl
            const int c = idx & 511;
            const int row = c >> 3, g = c & 7;
            const __nv_bfloat16* src = ((t4 & 1) ? qkvl : qkvh)
                + (size_t)(b * TT + t0 + row) * row3
                + EE + (t4 >> 1) * EE + h * HD + g * 8;
            cpa16(sb + AKH + t4 * 8192 + row * 128
                  + (((uint32_t)(g ^ (row & 7))) << 4), src);
        }
        if (tid < 64) {
            const int tk = t0 + tid;
            bool pm;
            if (mode == 1)      pm = (((const int*)pad)[b * TT + tk] != 0);
            else if (mode == 2) pm = (((const float*)pad)[b * TT + tk] != 0.f);
            else                pm = (((const unsigned char*)pad)[b * TT + tk] != 0);
            sbias[tid] = pm ? -1e30f : 0.f;
        }
        cpa_commit(); cpa_wait0();
        __syncthreads();

        // ---- S = Q K^T (bf16x3) ----
        float s[8][4];
        #pragma unroll
        for (int nt = 0; nt < 8; nt++)
            #pragma unroll
            for (int i = 0; i < 4; i++) s[nt][i] = 0.f;

        #pragma unroll
        for (int kc = 0; kc < 4; kc++) {
            uint32_t bh[4][4], bl[4][4];
            #pragma unroll
            for (int g2 = 0; g2 < 4; g2++) {
                const int row = 16 * g2 + r15;
                const uint32_t a = (uint32_t)row * 128
                    + (((uint32_t)((2 * kc + hs) ^ (row & 7))) << 4);
                ldsm4(bh[g2], sb + AKH + a);
                ldsm4(bl[g2], sb + AKL + a);
            }
            #pragma unroll
            for (int g2 = 0; g2 < 4; g2++) {
                mma16816(s[2*g2],   qhf[kc], bh[g2][0], bh[g2][2]);
                mma16816(s[2*g2+1], qhf[kc], bh[g2][1], bh[g2][3]);
            }
            #pragma unroll
            for (int g2 = 0; g2 < 4; g2++) {
                mma16816(s[2*g2],   qhf[kc], bl[g2][0], bl[g2][2]);
                mma16816(s[2*g2+1], qhf[kc], bl[g2][1], bl[g2][3]);
            }
            #pragma unroll
            for (int g2 = 0; g2 < 4; g2++) {
                mma16816(s[2*g2],   qlf[kc], bh[g2][0], bh[g2][2]);
                mma16816(s[2*g2+1], qlf[kc], bh[g2][1], bh[g2][3]);
            }
        }

        // ---- softmax (base-2, online) ----
        float ml0 = -1e30f, ml1 = -1e30f;
        const int diag = (kt == qt);
        #pragma unroll
        for (int nt = 0; nt < 8; nt++) {
            #pragma unroll
            for (int i = 0; i < 4; i++) {
                const int col = nt * 8 + 2 * (lane & 3) + (i & 1);
                float v = s[nt][i] * cst + sbias[col];
                if (diag) {
                    const int kg = t0 + col;
                    const int qg = q0 + 16 * w + gr + (i >> 1) * 8;
                    if (kg > qg) v = -1e30f;
                }
                s[nt][i] = v;
                if (i < 2) ml0 = fmaxf(ml0, v); else ml1 = fmaxf(ml1, v);
            }
        }
        ml0 = fmaxf(ml0, __shfl_xor_sync(0xffffffffu, ml0, 1));
        ml0 = fmaxf(ml0, __shfl_xor_sync(0xffffffffu, ml0, 2));
        ml1 = fmaxf(ml1, __shfl_xor_sync(0xffffffffu, ml1, 1));
        ml1 = fmaxf(ml1, __shfl_xor_sync(0xffffffffu, ml1, 2));
        const float mn0 = fmaxf(m2[0], ml0), mn1 = fmaxf(m2[1], ml1);
        const float al0 = ex2f(m2[0] - mn0), al1 = ex2f(m2[1] - mn1);
        m2[0] = mn0; m2[1] = mn1;

        float rs0 = 0.f, rs1 = 0.f;
        #pragma unroll
        for (int nt = 0; nt < 8; nt++) {
            #pragma unroll
            for (int i = 0; i < 4; i++) {
                const float p = ex2f(s[nt][i] - ((i < 2) ? mn0 : mn1));
                s[nt][i] = p;
                if (i < 2) rs0 += p; else rs1 += p;
            }
        }
        rs0 += __shfl_xor_sync(0xffffffffu, rs0, 1);
        rs0 += __shfl_xor_sync(0xffffffffu, rs0, 2);
        rs1 += __shfl_xor_sync(0xffffffffu, rs1, 1);
        rs1 += __shfl_xor_sync(0xffffffffu, rs1, 2);
        lsum[0] = lsum[0] * al0 + rs0;
        lsum[1] = lsum[1] * al1 + rs1;
        #pragma unroll
        for (int nt = 0; nt < 8; nt++) {
            o[nt][0] *= al0; o[nt][1] *= al0;
            o[nt][2] *= al1; o[nt][3] *= al1;
        }

        // ---- P fragments hi/lo ----
        uint32_t pah[4][4], pal[4][4];
        #pragma unroll
        for (int c = 0; c < 4; c++) {
            #pragma unroll
            for (int j = 0; j < 4; j++) {
                const int nt = 2 * c + (j >> 1);
                const int i0 = (j & 1) * 2;
                const float x = s[nt][i0], y = s[nt][i0 + 1];
                __nv_bfloat162 hp = __float22bfloat162_rn(make_float2(x, y));
                __nv_bfloat162 lp = __float22bfloat162_rn(make_float2(
                    x - __low2float(hp), y - __high2float(hp)));
                pah[c][j] = *reinterpret_cast<uint32_t*>(&hp);
                pal[c][j] = *reinterpret_cast<uint32_t*>(&lp);
            }
        }

        // ---- O += P V ----
        #pragma unroll
        for (int c = 0; c < 4; c++) {
            uint32_t vh[4][4], vl[4][4];
            #pragma unroll
            for (int g2 = 0; g2 < 4; g2++) {
                const int row = 16 * c + r15;
                const uint32_t a = (uint32_t)row * 128
                    + (((uint32_t)((2 * g2 + hs) ^ (row & 7))) << 4);
                ldsm4t(vh[g2], sb + AVH + a);
                ldsm4t(vl[g2], sb + AVL + a);
            }
            #pragma unroll
            for (int g2 = 0; g2 < 4; g2++) {
                mma16816(o[2*g2],   pah[c], vh[g2][0], vh[g2][1]);
                mma16816(o[2*g2+1], pah[c], vh[g2][2], vh[g2][3]);
            }
            #pragma unroll
            for (int g2 = 0; g2 < 4; g2++) {
                mma16816(o[2*g2],   pal[c], vh[g2][0], vh[g2][1]);
                mma16816(o[2*g2+1], pal[c], vh[g2][2], vh[g2][3]);
            }
            #pragma unroll
            for (int g2 = 0; g2 < 4; g2++) {
                mma16816(o[2*g2],   pah[c], vl[g2][0], vl[g2][1]);
                mma16816(o[2*g2+1], pah[c], vl[g2][2], vl[g2][3]);
            }
        }
    }

    // ---- epilogue: normalize, split hi/lo, write ----
    const float inv0 = 1.f / lsum[0], inv1 = 1.f / lsum[1];
    #pragma unroll
    for (int r = 0; r < 2; r++) {
        const int row = q0 + 16 * w + gr + 8 * r;
        const float inv = r ? inv1 : inv0;
        const size_t base = (size_t)(b * TT + row) * EE + h * HD + 2 * (lane & 3);
        #pragma unroll
        for (int nt = 0; nt < 8; nt++) {
            const float x = o[nt][2 * r] * inv;
            const float y = o[nt][2 * r + 1] * inv;
            __nv_bfloat162 hp = __float22bfloat162_rn(make_float2(x, y));
            __nv_bfloat162 lp = __float22bfloat162_rn(make_float2(
                x - __low2float(hp), y - __high2float(hp)));
            *(__nv_bfloat162*)(outh + base + nt * 8) = hp;
            *(__nv_bfloat162*)(outl + base + nt * 8) = lp;
        }
    }
}

// ---------------- LayerNorm in-place (+ optional hi/lo emit) ----------------
template <int HL>
__global__ __launch_bounds__(256) void ln_kernel(
    float* __restrict__ X, const float* __restrict__ w,
    const float* __restrict__ bias,
    __nv_bfloat16* __restrict__ Yh, __nv_bfloat16* __restrict__ Yl)
{
    __shared__ float red[8];
    const int row = blockIdx.x, tid = threadIdx.x;
    float4* xr = (float4*)(X + (size_t)row * EE);
    float4 v = xr[tid];

    float s = v.x + v.y + v.z + v.w;
    #pragma unroll
    for (int o = 16; o; o >>= 1) s += __shfl_xor_sync(0xffffffffu, s, o);
    if ((tid & 31) == 0) red[tid >> 5] = s;
    __syncthreads();
    float tot = red[0] + red[1] + red[2] + red[3] + red[4] + red[5] + red[6] + red[7];
    const float mean = tot * (1.f / EE);

    float dx = v.x - mean, dy = v.y - mean, dz = v.z - mean, dw = v.w - mean;
    float s2 = dx * dx + dy * dy + dz * dz + dw * dw;
    __syncthreads();
    #pragma unroll
    for (int o = 16; o; o >>= 1) s2 += __shfl_xor_sync(0xffffffffu, s2, o);
    if ((tid & 31) == 0) red[tid >> 5] = s2;
    __syncthreads();
    float tot2 = red[0] + red[1] + red[2] + red[3] + red[4] + red[5] + red[6] + red[7];
    const float var = tot2 * (1.f / EE);
    const float inv = rsqrtf(var + 1e-12f);

    float4 wv = ((const float4*)w)[tid];
    float4 bv = ((const float4*)bias)[tid];
    float4 r;
    r.x = dx * inv * wv.x + bv.x;
    r.y = dy * inv * wv.y + bv.y;
    r.z = dz * inv * wv.z + bv.z;
    r.w = dw * inv * wv.w + bv.w;
    xr[tid] = r;
    if (HL) {
        const size_t base = (size_t)row * EE + tid * 4;
        __nv_bfloat162 h01 = __float22bfloat162_rn(make_float2(r.x, r.y));
        __nv_bfloat162 h23 = __float22bfloat162_rn(make_float2(r.z, r.w));
        __nv_bfloat162 l01 = __float22bfloat162_rn(make_float2(
            r.x - __low2float(h01), r.y - __high2float(h01)));
        __nv_bfloat162 l23 = __float22bfloat162_rn(make_float2(
            r.z - __low2float(h23), r.w - __high2float(h23)));
        *(__nv_bfloat162*)(Yh + base)     = h01;
        *(__nv_bfloat162*)(Yh + base + 2) = h23;
        *(__nv_bfloat162*)(Yl + base)     = l01;
        *(__nv_bfloat162*)(Yl + base + 2) = l23;
    }
}

// ---------------- launch ----------------
extern "C" void kernel_launch(void* const* d_in, const int* in_sizes, int n_in,
                              void* d_out, int out_size)
{
    const float* x     = (const float*)d_in[0];
    const float* in_w  = (const float*)d_in[1];
    const float* in_b  = (const float*)d_in[2];
    const float* out_w = (const float*)d_in[3];
    const float* out_b = (const float*)d_in[4];
    const float* fc1_w = (const float*)d_in[5];
    const float* fc1_b = (const float*)d_in[6];
    const float* fc2_w = (const float*)d_in[7];
    const float* fc2_b = (const float*)d_in[8];
    const float* ln1_w = (const float*)d_in[9];
    const float* ln1_b = (const float*)d_in[10];
    const float* ln2_w = (const float*)d_in[11];
    const float* ln2_b = (const float*)d_in[12];
    const void*  pad   = d_in[13];
    float* out = (float*)d_out;

    float* p_y1;
    __nv_bfloat16 *p_qh, *p_ql, *p_xh, *p_xl, *p_ah, *p_al,
        *p_y1h, *p_y1l, *p_fh, *p_fl;
    __nv_bfloat16 *p_wih, *p_wil, *p_woh, *p_wol, *p_w1h, *p_w1l, *p_w2h, *p_w2l;
    cudaGetSymbolAddress((void**)&p_y1,  g_y1);
    cudaGetSymbolAddress((void**)&p_qh,  g_qh);  cudaGetSymbolAddress((void**)&p_ql,  g_ql);
    cudaGetSymbolAddress((void**)&p_xh,  g_xh);  cudaGetSymbolAddress((void**)&p_xl,  g_xl);
    cudaGetSymbolAddress((void**)&p_ah,  g_ah);  cudaGetSymbolAddress((void**)&p_al,  g_al);
    cudaGetSymbolAddress((void**)&p_y1h, g_y1h); cudaGetSymbolAddress((void**)&p_y1l, g_y1l);
    cudaGetSymbolAddress((void**)&p_fh,  g_fh);  cudaGetSymbolAddress((void**)&p_fl,  g_fl);
    cudaGetSymbolAddress((void**)&p_wih, g_wih); cudaGetSymbolAddress((void**)&p_wil, g_wil);
    cudaGetSymbolAddress((void**)&p_woh, g_woh); cudaGetSymbolAddress((void**)&p_wol, g_wol);
    cudaGetSymbolAddress((void**)&p_w1h, g_w1h); cudaGetSymbolAddress((void**)&p_w1l, g_w1l);
    cudaGetSymbolAddress((void**)&p_w2h, g_w2h); cudaGetSymbolAddress((void**)&p_w2l, g_w2l);

    cudaFuncSetAttribute(gemm_hl<0,0,1>, cudaFuncAttributeMaxDynamicSharedMemorySize, SMEMG);
    cudaFuncSetAttribute(gemm_hl<0,1,0>, cudaFuncAttributeMaxDynamicSharedMemorySize, SMEMG);
    cudaFuncSetAttribute(gemm_hl<1,0,1>, cudaFuncAttributeMaxDynamicSharedMemorySize, SMEMG);
    cudaFuncSetAttribute(attn_mma, cudaFuncAttributeMaxDynamicSharedMemorySize, ATT_SMEM);

    probe_mask<<<1, 256>>>((const unsigned char*)pad);

    convert_hl<<<(MM * EE / 4 + 255) / 256, 256>>>(x, p_xh, p_xl, MM * EE / 4);
    convert_hl<<<(3 * EE * EE / 4 + 255) / 256, 256>>>(in_w,  p_wih, p_wil, 3 * EE * EE / 4);
    convert_hl<<<(EE * EE / 4 + 255) / 256, 256>>>(out_w, p_woh, p_wol, EE * EE / 4);
    convert_hl<<<(FFD * EE / 4 + 255) / 256, 256>>>(fc1_w, p_w1h, p_w1l, FFD * EE / 4);
    convert_hl<<<(EE * FFD / 4 + 255) / 256, 256>>>(fc2_w, p_w2h, p_w2l, EE * FFD / 4);

    // 1. QKV projection -> bf16 hi/lo
    gemm_hl<0,0,1><<<dim3(3 * EE / 128, MM / 128), 128, SMEMG>>>(
        p_xh, p_xl, p_wih, p_wil, in_b, nullptr,
        nullptr, p_qh, p_ql, MM, 3 * EE, EE);

    // 2. tensor-core flash attention -> hi/lo
    attn_mma<<<dim3(TT / 64, HH, BB), 128, ATT_SMEM>>>(p_qh, p_ql, pad, p_ah, p_al);

    // 3. out projection + bias + residual(x) -> fp32 y1
    gemm_hl<0,1,0><<<dim3(EE / 128, MM / 128), 128, SMEMG>>>(
        p_ah, p_al, p_woh, p_wol, out_b, x,
        p_y1, nullptr, nullptr, MM, EE, EE);

    // 4. LN1 in-place + hi/lo emit
    ln_kernel<1><<<MM, 256>>>(p_y1, ln1_w, ln1_b, p_y1h, p_y1l);

    // 5. FC1 + ReLU -> hi/lo only
    gemm_hl<1,0,1><<<dim3(FFD / 128, MM / 128), 128, SMEMG>>>(
        p_y1h, p_y1l, p_w1h, p_w1l, fc1_b, nullptr,
        nullptr, p_fh, p_fl, MM, FFD, EE);

    // 6. FC2 + bias + residual(y1) -> d_out fp32
    gemm_hl<0,1,0><<<dim3(EE / 128, MM / 128), 128, SMEMG>>>(
        p_fh, p_fl, p_w2h, p_w2l, fc2_b, p_y1,
        out, nullptr, nullptr, MM, EE, FFD);

    // 7. LN2 in-place on d_out
    ln_kernel<0><<<MM, 256>>>(out, ln2_w, ln2_b, nullptr, nullptr);
}

// round 13
// speedup vs baseline: 4.5995x; 1.0148x over previous
#include <cuda_runtime.h>
#include <cuda_bf16.h>
#include <cstdint>

#define BB 8
#define TT 1024
#define EE 1024
#define HH 16
#define HD 64
#define FFD 4096
#define MM (BB*TT)          // 8192 rows
#define SCALE 0.125f        // HD^-0.5

// ---------------- scratch (device globals: allocation-free) ----------------
static __device__ float g_y1[MM * EE];        // fp32 (LN1 out, FC2 residual)
static __device__ __nv_bfloat16 g_qh[MM * 3 * EE], g_ql[MM * 3 * EE]; // qkv hi/lo
static __device__ __nv_bfloat16 g_xh[MM * EE],  g_xl[MM * EE];    // x hi/lo
static __device__ __nv_bfloat16 g_ah[MM * EE],  g_al[MM * EE];    // attn out hi/lo
static __device__ __nv_bfloat16 g_y1h[MM * EE], g_y1l[MM * EE];   // LN1 out hi/lo
static __device__ __nv_bfloat16 g_fh[MM * FFD], g_fl[MM * FFD];   // FC1 out hi/lo
static __device__ __nv_bfloat16 g_wih[3*EE*EE], g_wil[3*EE*EE];
static __device__ __nv_bfloat16 g_woh[EE*EE],   g_wol[EE*EE];
static __device__ __nv_bfloat16 g_w1h[FFD*EE],  g_w1l[FFD*EE];
static __device__ __nv_bfloat16 g_w2h[EE*FFD],  g_w2l[EE*FFD];
static __device__ int g_mask_mode;            // 0=u8, 1=i32, 2=f32

// ================= PTX helpers =================
__device__ __forceinline__ uint32_t smem_u32(const void* p) {
    uint32_t a;
    asm("{ .reg .u64 t; cvta.to.shared.u64 t, %1; cvt.u32.u64 %0, t; }"
        : "=r"(a) : "l"(p));
    return a;
}
__device__ __forceinline__ void ldsm4(uint32_t* r, uint32_t addr) {
    asm volatile("ldmatrix.sync.aligned.m8n8.x4.shared.b16 {%0,%1,%2,%3}, [%4];"
                 : "=r"(r[0]), "=r"(r[1]), "=r"(r[2]), "=r"(r[3]) : "r"(addr));
}
__device__ __forceinline__ void ldsm4t(uint32_t* r, uint32_t addr) {
    asm volatile("ldmatrix.sync.aligned.m8n8.x4.trans.shared.b16 {%0,%1,%2,%3}, [%4];"
                 : "=r"(r[0]), "=r"(r[1]), "=r"(r[2]), "=r"(r[3]) : "r"(addr));
}
__device__ __forceinline__ void mma16816(float* d, const uint32_t* a,
                                         uint32_t b0, uint32_t b1) {
    asm volatile(
        "mma.sync.aligned.m16n8k16.row.col.f32.bf16.bf16.f32 "
        "{%0,%1,%2,%3}, {%4,%5,%6,%7}, {%8,%9}, {%0,%1,%2,%3};"
        : "+f"(d[0]), "+f"(d[1]), "+f"(d[2]), "+f"(d[3])
        : "r"(a[0]), "r"(a[1]), "r"(a[2]), "r"(a[3]), "r"(b0), "r"(b1));
}
__device__ __forceinline__ void cpa16(uint32_t dst, const void* src) {
    asm volatile("cp.async.cg.shared.global [%0], [%1], 16;" :: "r"(dst), "l"(src));
}
__device__ __forceinline__ void cpa_commit() {
    asm volatile("cp.async.commit_group;" ::: "memory");
}
__device__ __forceinline__ void cpa_wait2() {
    asm volatile("cp.async.wait_group 2;" ::: "memory");
}
__device__ __forceinline__ void cpa_wait1() {
    asm volatile("cp.async.wait_group 1;" ::: "memory");
}
__device__ __forceinline__ void cpa_wait0() {
    asm volatile("cp.async.wait_group 0;" ::: "memory");
}
__device__ __forceinline__ float ex2f(float x) {
    float y;
    asm("ex2.approx.ftz.f32 %0, %1;" : "=f"(y) : "f"(x));
    return y;
}

// ---------------- mask dtype probe ----------------
__global__ void probe_mask(const unsigned char* __restrict__ p) {
    __shared__ int cnt[4];
    if (threadIdx.x < 4) cnt[threadIdx.x] = 0;
    __syncthreads();
    int local[4] = {0, 0, 0, 0};
    for (int i = threadIdx.x; i < 8192; i += blockDim.x)
        if (p[i]) local[i & 3]++;
    #pragma unroll
    for (int c = 0; c < 4; c++)
        if (local[c]) atomicAdd(&cnt[c], local[c]);
    __syncthreads();
    if (threadIdx.x == 0) {
        int c0 = cnt[0], c1 = cnt[1], c2 = cnt[2], c3 = cnt[3];
        int mode = 0;
        if (c0 > 0 && c1 == 0 && c2 == 0 && c3 == 0) mode = 1;
        else if (c0 == 0 && c1 == 0 && (c2 > 0 || c3 > 0)) mode = 2;
        g_mask_mode = mode;
    }
}

// ---------------- fp32 -> bf16 hi/lo split ----------------
__global__ __launch_bounds__(256) void convert_hl(
    const float* __restrict__ in, __nv_bfloat16* __restrict__ h,
    __nv_bfloat16* __restrict__ l, int n4)
{
    int i = blockIdx.x * blockDim.x + threadIdx.x;
    if (i >= n4) return;
    float4 v = ((const float4*)in)[i];
    __nv_bfloat162 h01 = __float22bfloat162_rn(make_float2(v.x, v.y));
    __nv_bfloat162 h23 = __float22bfloat162_rn(make_float2(v.z, v.w));
    __nv_bfloat162 l01 = __float22bfloat162_rn(make_float2(
        v.x - __low2float(h01), v.y - __high2float(h01)));
    __nv_bfloat162 l23 = __float22bfloat162_rn(make_float2(
        v.z - __low2float(h23), v.w - __high2float(h23)));
    ((__nv_bfloat162*)h)[2*i]   = h01;
    ((__nv_bfloat162*)h)[2*i+1] = h23;
    ((__nv_bfloat162*)l)[2*i]   = l01;
    ((__nv_bfloat162*)l)[2*i+1] = l23;
}

// =================================================================
// Pure-bf16 HMMA GEMM: C = act(A @ W^T + bias (+R))
// =================================================================
#define STG_T 8192
#define STG_ALL 32768
#define SMEMG (3 * STG_ALL)

#define MMAS(AF, BF) do { \
    _Pragma("unroll") \
    for (int mt = 0; mt < 4; mt++) { \
        _Pragma("unroll") \
        for (int g = 0; g < 4; g++) { \
            mma16816(acc[mt][2*g],   AF[mt], BF[g][0], BF[g][2]); \
            mma16816(acc[mt][2*g+1], AF[mt], BF[g][1], BF[g][3]); \
        } \
    } \
} while (0)

#define LOAD_STAGE(stg, ch) do { \
    const uint32_t _base = sb + (stg) * STG_ALL + l_dst0; \
    const int _ko = (ch) * 32 + l_k; \
    _Pragma("unroll") \
    for (int i = 0; i < 16; i++) { \
        const int t = i >> 2; \
        const int rr = l_row + (i & 3) * 32; \
        const __nv_bfloat16* _s = \
            (t < 2 ? gA[t] : gW[t - 2]) + (size_t)rr * K + _ko; \
        cpa16(_base + t * STG_T + (i & 3) * 2048, _s); \
    } \
} while (0)

template <int RELU, int RES, int OUTHL>
__global__ __launch_bounds__(128) void gemm_hl(
    const __nv_bfloat16* __restrict__ Ah, const __nv_bfloat16* __restrict__ Al,
    const __nv_bfloat16* __restrict__ Wh, const __nv_bfloat16* __restrict__ Wl,
    const float* __restrict__ bias, const float* __restrict__ R,
    float* __restrict__ Cf, __nv_bfloat16* __restrict__ Ch,
    __nv_bfloat16* __restrict__ Cl, int M, int N, int K)
{
    extern __shared__ char smem[];
    const uint32_t sb = smem_u32(smem);
    const int tid = threadIdx.x, lane = tid & 31, wid = tid >> 5;
    const int wm = wid & 1, wn = wid >> 1;
    const int m0 = blockIdx.y * 128, n0 = blockIdx.x * 128;

    const uint32_t l_sw = (uint32_t)(((tid & 3) ^ ((tid >> 2) & 3) ^ ((tid >> 4) & 3)) << 4);
    const uint32_t l_dst0 = (uint32_t)((tid >> 2) << 6) + l_sw;
    const int l_row = tid >> 2;
    const int l_k   = (tid & 3) * 8;
    const __nv_bfloat16* gA[2] = {Ah + (size_t)m0 * K, Al + (size_t)m0 * K};
    const __nv_bfloat16* gW[2] = {Wh + (size_t)n0 * K, Wl + (size_t)n0 * K};

    const int r15 = lane & 15;
    const int hs  = lane >> 4;
    const uint32_t xorc = (uint32_t)((r15 & 3) ^ ((r15 >> 2) & 3));
    const uint32_t aro = (uint32_t)(wm * 64 + r15) * 64;
    const uint32_t bro = (uint32_t)(wn * 64 + r15) * 64;

    float acc[4][8][4];
    #pragma unroll
    for (int a = 0; a < 4; a++)
        #pragma unroll
        for (int b = 0; b < 8; b++)
            #pragma unroll
            for (int c = 0; c < 4; c++) acc[a][b][c] = 0.f;

    const int nch = K >> 5;

    LOAD_STAGE(0, 0); cpa_commit();
    LOAD_STAGE(1, 1); cpa_commit();

    int stg = 0;
    for (int ch = 0; ch < nch; ch++) {
        cpa_wait1();
        __syncthreads();
        const int nc = ch + 2;
        if (nc < nch) {
            const int ns = (stg == 0) ? 2 : stg - 1;
            LOAD_STAGE(ns, nc);
        }
        cpa_commit();

        const uint32_t st = sb + stg * STG_ALL;
        #pragma unroll
        for (int kk = 0; kk < 2; kk++) {
            const uint32_t ksw = (((uint32_t)(2 * kk + hs)) ^ xorc) << 4;
            uint32_t af[4][4], bf[4][4], cf2[4][4];
            #pragma unroll
            for (int mt = 0; mt < 4; mt++)
                ldsm4(af[mt], st + 0 * STG_T + aro + mt * 1024 + ksw);
            #pragma unroll
            for (int g = 0; g < 4; g++)
                ldsm4(bf[g], st + 2 * STG_T + bro + g * 1024 + ksw);
            MMAS(af, bf);
            #pragma unroll
            for (int g = 0; g < 4; g++)
                ldsm4(cf2[g], st + 3 * STG_T + bro + g * 1024 + ksw);
            MMAS(af, cf2);
            #pragma unroll
            for (int mt = 0; mt < 4; mt++)
                ldsm4(af[mt], st + 1 * STG_T + aro + mt * 1024 + ksw);
            MMAS(af, bf);
        }
        stg = (stg == 2) ? 0 : stg + 1;
    }

    const int gr = lane >> 2;
    const int gc = (lane & 3) * 2;
    #pragma unroll
    for (int mt = 0; mt < 4; mt++) {
        #pragma unroll
        for (int half = 0; half < 2; half++) {
            const int m = m0 + wm * 64 + mt * 16 + gr + half * 8;
            #pragma unroll
            for (int nt = 0; nt < 8; nt++) {
                const int col = n0 + wn * 64 + nt * 8 + gc;
                float2 bv = *(const float2*)(bias + col);
                float ox = acc[mt][nt][2*half + 0] + bv.x;
                float oy = acc[mt][nt][2*half + 1] + bv.y;
                if (RES) {
                    float2 rv = *(const float2*)(R + (size_t)m * N + col);
                    ox += rv.x; oy += rv.y;
                }
                if (RELU) { ox = fmaxf(ox, 0.f); oy = fmaxf(oy, 0.f); }
                if (OUTHL) {
                    __nv_bfloat162 hp = __float22bfloat162_rn(make_float2(ox, oy));
                    __nv_bfloat162 lp = __float22bfloat162_rn(make_float2(
                        ox - __low2float(hp), oy - __high2float(hp)));
                    *(__nv_bfloat162*)(Ch + (size_t)m * N + col) = hp;
                    *(__nv_bfloat162*)(Cl + (size_t)m * N + col) = lp;
                } else {
                    *(float2*)(Cf + (size_t)m * N + col) = make_float2(ox, oy);
                }
            }
        }
    }
}

// =================================================================
// Tensor-core flash attention, 2-stage double-buffered K/V pipeline.
// 128 threads (4 warps), 64 queries/block, grid (16, 16, 8).
// smem: Qh Ql (16 KB) | KV stage0 (32 KB) | KV stage1 (32 KB) | bias[2][64]
// =================================================================
#define AQH 0
#define AQL 8192
#define AKV 16384
#define KVSTG 32768
#define ABIAS (AKV + 2 * KVSTG)     // 81920
#define ATT_SMEM (ABIAS + 512)

// stage tile kt into KV stage st (cp.async) + padding bias (plain store)
#define LOADKV(st_, kt_) do { \
    const int _t0 = (kt_) * 64; \
    const uint32_t _kb = sb + AKV + (st_) * KVSTG; \
    _Pragma("unroll") \
    for (int i = 0; i < 16; i++) { \
        const int idx = i * 128 + tid; \
        const int t4 = idx >> 9; \
        const int c = idx & 511; \
        const int row = c >> 3, g = c & 7; \
        const __nv_bfloat16* src = ((t4 & 1) ? qkvl : qkvh) \
            + (size_t)(b * TT + _t0 + row) * row3 \
            + EE + (t4 >> 1) * EE + h * HD + g * 8; \
        cpa16(_kb + t4 * 8192 + row * 128 \
              + (((uint32_t)(g ^ (row & 7))) << 4), src); \
    } \
    if (tid < 64) { \
        const int tk = _t0 + tid; \
        bool pm; \
        if (mode == 1)      pm = (((const int*)pad)[b * TT + tk] != 0); \
        else if (mode == 2) pm = (((const float*)pad)[b * TT + tk] != 0.f); \
        else                pm = (((const unsigned char*)pad)[b * TT + tk] != 0); \
        sbias[((st_) << 6) + tid] = pm ? -1e30f : 0.f; \
    } \
} while (0)

__global__ __launch_bounds__(128) void attn_mma(
    const __nv_bfloat16* __restrict__ qkvh,
    const __nv_bfloat16* __restrict__ qkvl,
    const void* __restrict__ pad,
    __nv_bfloat16* __restrict__ outh, __nv_bfloat16* __restrict__ outl)
{
    extern __shared__ char sm[];
    const uint32_t sb = smem_u32(sm);
    float* sbias = (float*)(sm + ABIAS);

    const int tid = threadIdx.x, lane = tid & 31, w = tid >> 5;
    // LPT: longest (highest-qt) blocks first
    const int qt = (int)gridDim.x - 1 - (int)blockIdx.x;
    const int h = blockIdx.y, b = blockIdx.z;
    const int q0 = qt * 64;
    const int row3 = 3 * EE;
    const int mode = g_mask_mode;
    const int gr = lane >> 2;
    const int r15 = lane & 15;
    const int hs = lane >> 4;

    // ---- stage Q (hi/lo), then prefetch KV tiles 0 and 1 ----
    #pragma unroll
    for (int i = 0; i < 8; i++) {
        const int idx = i * 128 + tid;
        const int t = idx >> 9;
        const int c = idx & 511;
        const int row = c >> 3, g = c & 7;
        const __nv_bfloat16* src = (t ? qkvl : qkvh)
            + (size_t)(b * TT + q0 + row) * row3 + h * HD + g * 8;
        cpa16(sb + t * 8192 + row * 128 + (((uint32_t)(g ^ (row & 7))) << 4), src);
    }
    cpa_commit();                       // Gq
    LOADKV(0, 0); cpa_commit();         // G0
    if (qt >= 1) { LOADKV(1, 1); cpa_commit(); }   // G1
    if (qt >= 1) cpa_wait2(); else cpa_wait1();    // Q ready
    __syncthreads();

    // Q fragments -> registers (reused every k-tile)
    uint32_t qhf[4][4], qlf[4][4];
    #pragma unroll
    for (int kc = 0; kc < 4; kc++) {
        const int row = 16 * w + r15;
        const uint32_t a = (uint32_t)row * 128
            + (((uint32_t)((2 * kc + hs) ^ (row & 7))) << 4);
        ldsm4(qhf[kc], sb + AQH + a);
        ldsm4(qlf[kc], sb + AQL + a);
    }

    float m2[2] = {-1e30f, -1e30f};
    float lsum[2] = {0.f, 0.f};
    float o[8][4];
    #pragma unroll
    for (int nt = 0; nt < 8; nt++)
        #pragma unroll
        for (int i = 0; i < 4; i++) o[nt][i] = 0.f;

    const float cst = SCALE * 1.44269504f;   // scale * log2(e)

    for (int kt = 0; kt <= qt; kt++) {
        if (kt == qt) cpa_wait0(); else cpa_wait1();
        __syncthreads();

        const int st = kt & 1;
        const uint32_t kvb = sb + AKV + st * KVSTG;
        const float* sbst = sbias + (st << 6);
        const int t0 = kt * 64;

        // ---- S = Q K^T (bf16x3) ----
        float s[8][4];
        #pragma unroll
        for (int nt = 0; nt < 8; nt++)
            #pragma unroll
            for (int i = 0; i < 4; i++) s[nt][i] = 0.f;

        #pragma unroll
        for (int kc = 0; kc < 4; kc++) {
            uint32_t bh[4][4], bl[4][4];
            #pragma unroll
            for (int g2 = 0; g2 < 4; g2++) {
                const int row = 16 * g2 + r15;
                const uint32_t a = (uint32_t)row * 128
                    + (((uint32_t)((2 * kc + hs) ^ (row & 7))) << 4);
                ldsm4(bh[g2], kvb + a);            // Kh
                ldsm4(bl[g2], kvb + 8192 + a);     // Kl
            }
            #pragma unroll
            for (int g2 = 0; g2 < 4; g2++) {
                mma16816(s[2*g2],   qhf[kc], bh[g2][0], bh[g2][2]);
                mma16816(s[2*g2+1], qhf[kc], bh[g2][1], bh[g2][3]);
            }
            #pragma unroll
            for (int g2 = 0; g2 < 4; g2++) {
                mma16816(s[2*g2],   qhf[kc], bl[g2][0], bl[g2][2]);
                mma16816(s[2*g2+1], qhf[kc], bl[g2][1], bl[g2][3]);
            }
            #pragma unroll
            for (int g2 = 0; g2 < 4; g2++) {
                mma16816(s[2*g2],   qlf[kc], bh[g2][0], bh[g2][2]);
                mma16816(s[2*g2+1], qlf[kc], bh[g2][1], bh[g2][3]);
            }
        }

        // ---- softmax (base-2, online) ----
        float ml0 = -1e30f, ml1 = -1e30f;
        const int diag = (kt == qt);
        #pragma unroll
        for (int nt = 0; nt < 8; nt++) {
            #pragma unroll
            for (int i = 0; i < 4; i++) {
                const int col = nt * 8 + 2 * (lane & 3) + (i & 1);
                float v = s[nt][i] * cst + sbst[col];
                if (diag) {
                    const int kg = t0 + col;
                    const int qg = q0 + 16 * w + gr + (i >> 1) * 8;
                    if (kg > qg) v = -1e30f;
                }
                s[nt][i] = v;
                if (i < 2) ml0 = fmaxf(ml0, v); else ml1 = fmaxf(ml1, v);
            }
        }
        ml0 = fmaxf(ml0, __shfl_xor_sync(0xffffffffu, ml0, 1));
        ml0 = fmaxf(ml0, __shfl_xor_sync(0xffffffffu, ml0, 2));
        ml1 = fmaxf(ml1, __shfl_xor_sync(0xffffffffu, ml1, 1));
        ml1 = fmaxf(ml1, __shfl_xor_sync(0xffffffffu, ml1, 2));
        const float mn0 = fmaxf(m2[0], ml0), mn1 = fmaxf(m2[1], ml1);
        const float al0 = ex2f(m2[0] - mn0), al1 = ex2f(m2[1] - mn1);
        m2[0] = mn0; m2[1] = mn1;

        float rs0 = 0.f, rs1 = 0.f;
        #pragma unroll
        for (int nt = 0; nt < 8; nt++) {
            #pragma unroll
            for (int i = 0; i < 4; i++) {
                const float p = ex2f(s[nt][i] - ((i < 2) ? mn0 : mn1));
                s[nt][i] = p;
                if (i < 2) rs0 += p; else rs1 += p;
            }
        }
        rs0 += __shfl_xor_sync(0xffffffffu, rs0, 1);
        rs0 += __shfl_xor_sync(0xffffffffu, rs0, 2);
        rs1 += __shfl_xor_sync(0xffffffffu, rs1, 1);
        rs1 += __shfl_xor_sync(0xffffffffu, rs1, 2);
        lsum[0] = lsum[0] * al0 + rs0;
        lsum[1] = lsum[1] * al1 + rs1;
        #pragma unroll
        for (int nt = 0; nt < 8; nt++) {
            o[nt][0] *= al0; o[nt][1] *= al0;
            o[nt][2] *= al1; o[nt][3] *= al1;
        }

        // ---- P fragments hi/lo ----
        uint32_t pah[4][4], pal[4][4];
        #pragma unroll
        for (int c = 0; c < 4; c++) {
            #pragma unroll
            for (int j = 0; j < 4; j++) {
                const int nt = 2 * c + (j >> 1);
                const int i0 = (j & 1) * 2;
                const float x = s[nt][i0], y = s[nt][i0 + 1];
                __nv_bfloat162 hp = __float22bfloat162_rn(make_float2(x, y));
                __nv_bfloat162 lp = __float22bfloat162_rn(make_float2(
                    x - __low2float(hp), y - __high2float(hp)));
                pah[c][j] = *reinterpret_cast<uint32_t*>(&hp);
                pal[c][j] = *reinterpret_cast<uint32_t*>(&lp);
            }
        }

        // ---- O += P V ----
        #pragma unroll
        for (int c = 0; c < 4; c++) {
            uint32_t vh[4][4], vl[4][4];
            #pragma unroll
            for (int g2 = 0; g2 < 4; g2++) {
                const int row = 16 * c + r15;
                const uint32_t a = (uint32_t)row * 128
                    + (((uint32_t)((2 * g2 + hs) ^ (row & 7))) << 4);
                ldsm4t(vh[g2], kvb + 16384 + a);   // Vh
                ldsm4t(vl[g2], kvb + 24576 + a);   // Vl
            }
            #pragma unroll
            for (int g2 = 0; g2 < 4; g2++) {
                mma16816(o[2*g2],   pah[c], vh[g2][0], vh[g2][1]);
                mma16816(o[2*g2+1], pah[c], vh[g2][2], vh[g2][3]);
            }
            #pragma unroll
            for (int g2 = 0; g2 < 4; g2++) {
                mma16816(o[2*g2],   pal[c], vh[g2][0], vh[g2][1]);
                mma16816(o[2*g2+1], pal[c], vh[g2][2], vh[g2][3]);
            }
            #pragma unroll
            for (int g2 = 0; g2 < 4; g2++) {
                mma16816(o[2*g2],   pah[c], vl[g2][0], vl[g2][1]);
                mma16816(o[2*g2+1], pah[c], vl[g2][2], vl[g2][3]);
            }
        }

        // prefetch tile kt+2 into the stage just consumed
        if (kt + 2 <= qt) {
            __syncthreads();            // everyone done reading stage st
            LOADKV(st, kt + 2);
            cpa_commit();
        }
    }

    // ---- epilogue: normalize, split hi/lo, write ----
    const float inv0 = 1.f / lsum[0], inv1 = 1.f / lsum[1];
    #pragma unroll
    for (int r = 0; r < 2; r++) {
        const int row = q0 + 16 * w + gr + 8 * r;
        const float inv = r ? inv1 : inv0;
        const size_t base = (size_t)(b * TT + row) * EE + h * HD + 2 * (lane & 3);
        #pragma unroll
        for (int nt = 0; nt < 8; nt++) {
            const float x = o[nt][2 * r] * inv;
            const float y = o[nt][2 * r + 1] * inv;
            __nv_bfloat162 hp = __float22bfloat162_rn(make_float2(x, y));
            __nv_bfloat162 lp = __float22bfloat162_rn(make_float2(
                x - __low2float(hp), y - __high2float(hp)));
            *(__nv_bfloat162*)(outh + base + nt * 8) = hp;
            *(__nv_bfloat162*)(outl + base + nt * 8) = lp;
        }
    }
}

// ---------------- LayerNorm in-place (+ optional hi/lo emit) ----------------
template <int HL>
__global__ __launch_bounds__(256) void ln_kernel(
    float* __restrict__ X, const float* __restrict__ w,
    const float* __restrict__ bias,
    __nv_bfloat16* __restrict__ Yh, __nv_bfloat16* __restrict__ Yl)
{
    __shared__ float red[8];
    const int row = blockIdx.x, tid = threadIdx.x;
    float4* xr = (float4*)(X + (size_t)row * EE);
    float4 v = xr[tid];

    float s = v.x + v.y + v.z + v.w;
    #pragma unroll
    for (int o = 16; o; o >>= 1) s += __shfl_xor_sync(0xffffffffu, s, o);
    if ((tid & 31) == 0) red[tid >> 5] = s;
    __syncthreads();
    float tot = red[0] + red[1] + red[2] + red[3] + red[4] + red[5] + red[6] + red[7];
    const float mean = tot * (1.f / EE);

    float dx = v.x - mean, dy = v.y - mean, dz = v.z - mean, dw = v.w - mean;
    float s2 = dx * dx + dy * dy + dz * dz + dw * dw;
    __syncthreads();
    #pragma unroll
    for (int o = 16; o; o >>= 1) s2 += __shfl_xor_sync(0xffffffffu, s2, o);
    if ((tid & 31) == 0) red[tid >> 5] = s2;
    __syncthreads();
    float tot2 = red[0] + red[1] + red[2] + red[3] + red[4] + red[5] + red[6] + red[7];
    const float var = tot2 * (1.f / EE);
    const float inv = rsqrtf(var + 1e-12f);

    float4 wv = ((const float4*)w)[tid];
    float4 bv = ((const float4*)bias)[tid];
    float4 r;
    r.x = dx * inv * wv.x + bv.x;
    r.y = dy * inv * wv.y + bv.y;
    r.z = dz * inv * wv.z + bv.z;
    r.w = dw * inv * wv.w + bv.w;
    xr[tid] = r;
    if (HL) {
        const size_t base = (size_t)row * EE + tid * 4;
        __nv_bfloat162 h01 = __float22bfloat162_rn(make_float2(r.x, r.y));
        __nv_bfloat162 h23 = __float22bfloat162_rn(make_float2(r.z, r.w));
        __nv_bfloat162 l01 = __float22bfloat162_rn(make_float2(
            r.x - __low2float(h01), r.y - __high2float(h01)));
        __nv_bfloat162 l23 = __float22bfloat162_rn(make_float2(
            r.z - __low2float(h23), r.w - __high2float(h23)));
        *(__nv_bfloat162*)(Yh + base)     = h01;
        *(__nv_bfloat162*)(Yh + base + 2) = h23;
        *(__nv_bfloat162*)(Yl + base)     = l01;
        *(__nv_bfloat162*)(Yl + base + 2) = l23;
    }
}

// ---------------- launch ----------------
extern "C" void kernel_launch(void* const* d_in, const int* in_sizes, int n_in,
                              void* d_out, int out_size)
{
    const float* x     = (const float*)d_in[0];
    const float* in_w  = (const float*)d_in[1];
    const float* in_b  = (const float*)d_in[2];
    const float* out_w = (const float*)d_in[3];
    const float* out_b = (const float*)d_in[4];
    const float* fc1_w = (const float*)d_in[5];
    const float* fc1_b = (const float*)d_in[6];
    const float* fc2_w = (const float*)d_in[7];
    const float* fc2_b = (const float*)d_in[8];
    const float* ln1_w = (const float*)d_in[9];
    const float* ln1_b = (const float*)d_in[10];
    const float* ln2_w = (const float*)d_in[11];
    const float* ln2_b = (const float*)d_in[12];
    const void*  pad   = d_in[13];
    float* out = (float*)d_out;

    float* p_y1;
    __nv_bfloat16 *p_qh, *p_ql, *p_xh, *p_xl, *p_ah, *p_al,
        *p_y1h, *p_y1l, *p_fh, *p_fl;
    __nv_bfloat16 *p_wih, *p_wil, *p_woh, *p_wol, *p_w1h, *p_w1l, *p_w2h, *p_w2l;
    cudaGetSymbolAddress((void**)&p_y1,  g_y1);
    cudaGetSymbolAddress((void**)&p_qh,  g_qh);  cudaGetSymbolAddress((void**)&p_ql,  g_ql);
    cudaGetSymbolAddress((void**)&p_xh,  g_xh);  cudaGetSymbolAddress((void**)&p_xl,  g_xl);
    cudaGetSymbolAddress((void**)&p_ah,  g_ah);  cudaGetSymbolAddress((void**)&p_al,  g_al);
    cudaGetSymbolAddress((void**)&p_y1h, g_y1h); cudaGetSymbolAddress((void**)&p_y1l, g_y1l);
    cudaGetSymbolAddress((void**)&p_fh,  g_fh);  cudaGetSymbolAddress((void**)&p_fl,  g_fl);
    cudaGetSymbolAddress((void**)&p_wih, g_wih); cudaGetSymbolAddress((void**)&p_wil, g_wil);
    cudaGetSymbolAddress((void**)&p_woh, g_woh); cudaGetSymbolAddress((void**)&p_wol, g_wol);
    cudaGetSymbolAddress((void**)&p_w1h, g_w1h); cudaGetSymbolAddress((void**)&p_w1l, g_w1l);
    cudaGetSymbolAddress((void**)&p_w2h, g_w2h); cudaGetSymbolAddress((void**)&p_w2l, g_w2l);

    cudaFuncSetAttribute(gemm_hl<0,0,1>, cudaFuncAttributeMaxDynamicSharedMemorySize, SMEMG);
    cudaFuncSetAttribute(gemm_hl<0,1,0>, cudaFuncAttributeMaxDynamicSharedMemorySize, SMEMG);
    cudaFuncSetAttribute(gemm_hl<1,0,1>, cudaFuncAttributeMaxDynamicSharedMemorySize, SMEMG);
    cudaFuncSetAttribute(attn_mma, cudaFuncAttributeMaxDynamicSharedMemorySize, ATT_SMEM);

    probe_mask<<<1, 256>>>((const unsigned char*)pad);

    convert_hl<<<(MM * EE / 4 + 255) / 256, 256>>>(x, p_xh, p_xl, MM * EE / 4);
    convert_hl<<<(3 * EE * EE / 4 + 255) / 256, 256>>>(in_w,  p_wih, p_wil, 3 * EE * EE / 4);
    convert_hl<<<(EE * EE / 4 + 255) / 256, 256>>>(out_w, p_woh, p_wol, EE * EE / 4);
    convert_hl<<<(FFD * EE / 4 + 255) / 256, 256>>>(fc1_w, p_w1h, p_w1l, FFD * EE / 4);
    convert_hl<<<(EE * FFD / 4 + 255) / 256, 256>>>(fc2_w, p_w2h, p_w2l, EE * FFD / 4);

    // 1. QKV projection -> bf16 hi/lo
    gemm_hl<0,0,1><<<dim3(3 * EE / 128, MM / 128), 128, SMEMG>>>(
        p_xh, p_xl, p_wih, p_wil, in_b, nullptr,
        nullptr, p_qh, p_ql, MM, 3 * EE, EE);

    // 2. tensor-core flash attention (double-buffered) -> hi/lo
    attn_mma<<<dim3(TT / 64, HH, BB), 128, ATT_SMEM>>>(p_qh, p_ql, pad, p_ah, p_al);

    // 3. out projection + bias + residual(x) -> fp32 y1
    gemm_hl<0,1,0><<<dim3(EE / 128, MM / 128), 128, SMEMG>>>(
        p_ah, p_al, p_woh, p_wol, out_b, x,
        p_y1, nullptr, nullptr, MM, EE, EE);

    // 4. LN1 in-place + hi/lo emit
    ln_kernel<1><<<MM, 256>>>(p_y1, ln1_w, ln1_b, p_y1h, p_y1l);

    // 5. FC1 + ReLU -> hi/lo only
    gemm_hl<1,0,1><<<dim3(FFD / 128, MM / 128), 128, SMEMG>>>(
        p_y1h, p_y1l, p_w1h, p_w1l, fc1_b, nullptr,
        nullptr, p_fh, p_fl, MM, FFD, EE);

    // 6. FC2 + bias + residual(y1) -> d_out fp32
    gemm_hl<0,1,0><<<dim3(EE / 128, MM / 128), 128, SMEMG>>>(
        p_fh, p_fl, p_w2h, p_w2l, fc2_b, p_y1,
        out, nullptr, nullptr, MM, EE, FFD);

    // 7. LN2 in-place on d_out
    ln_kernel<0><<<MM, 256>>>(out, ln2_w, ln2_b, nullptr, nullptr);
}

// round 14
// speedup vs baseline: 11.3504x; 2.4677x over previous
#include <cuda_runtime.h>
#include <cuda_fp16.h>
#include <cstdint>

#define BB 8
#define TT 1024
#define EE 1024
#define HH 16
#define HD 64
#define FFD 4096
#define MM (BB*TT)          // 8192 rows
#define SCALE 0.125f        // HD^-0.5

// ---------------- scratch (device globals: allocation-free) ----------------
static __device__ float  g_y1[MM * EE];          // fp32 (LN1 out, FC2 residual)
static __device__ __half g_q[MM * 3 * EE];       // qkv fp16
static __device__ __half g_x[MM * EE];           // x fp16
static __device__ __half g_a[MM * EE];           // attn out fp16
static __device__ __half g_y1h[MM * EE];         // LN1 out fp16
static __device__ __half g_f[MM * FFD];          // FC1 out fp16
static __device__ __half g_wi[3*EE*EE];
static __device__ __half g_wo[EE*EE];
static __device__ __half g_w1[FFD*EE];
static __device__ __half g_w2[EE*FFD];
static __device__ int g_mask_mode;               // 0=u8, 1=i32, 2=f32

// ================= PTX helpers =================
__device__ __forceinline__ uint32_t smem_u32(const void* p) {
    uint32_t a;
    asm("{ .reg .u64 t; cvta.to.shared.u64 t, %1; cvt.u32.u64 %0, t; }"
        : "=r"(a) : "l"(p));
    return a;
}
__device__ __forceinline__ void ldsm4(uint32_t* r, uint32_t addr) {
    asm volatile("ldmatrix.sync.aligned.m8n8.x4.shared.b16 {%0,%1,%2,%3}, [%4];"
                 : "=r"(r[0]), "=r"(r[1]), "=r"(r[2]), "=r"(r[3]) : "r"(addr));
}
__device__ __forceinline__ void ldsm4t(uint32_t* r, uint32_t addr) {
    asm volatile("ldmatrix.sync.aligned.m8n8.x4.trans.shared.b16 {%0,%1,%2,%3}, [%4];"
                 : "=r"(r[0]), "=r"(r[1]), "=r"(r[2]), "=r"(r[3]) : "r"(addr));
}
__device__ __forceinline__ void mma16816(float* d, const uint32_t* a,
                                         uint32_t b0, uint32_t b1) {
    asm volatile(
        "mma.sync.aligned.m16n8k16.row.col.f32.f16.f16.f32 "
        "{%0,%1,%2,%3}, {%4,%5,%6,%7}, {%8,%9}, {%0,%1,%2,%3};"
        : "+f"(d[0]), "+f"(d[1]), "+f"(d[2]), "+f"(d[3])
        : "r"(a[0]), "r"(a[1]), "r"(a[2]), "r"(a[3]), "r"(b0), "r"(b1));
}
__device__ __forceinline__ void cpa16(uint32_t dst, const void* src) {
    asm volatile("cp.async.cg.shared.global [%0], [%1], 16;" :: "r"(dst), "l"(src));
}
__device__ __forceinline__ void cpa_commit() {
    asm volatile("cp.async.commit_group;" ::: "memory");
}
__device__ __forceinline__ void cpa_wait2() {
    asm volatile("cp.async.wait_group 2;" ::: "memory");
}
__device__ __forceinline__ void cpa_wait1() {
    asm volatile("cp.async.wait_group 1;" ::: "memory");
}
__device__ __forceinline__ void cpa_wait0() {
    asm volatile("cp.async.wait_group 0;" ::: "memory");
}
__device__ __forceinline__ float ex2f(float x) {
    float y;
    asm("ex2.approx.ftz.f32 %0, %1;" : "=f"(y) : "f"(x));
    return y;
}
__device__ __forceinline__ uint32_t packh2(float x, float y) {
    __half2 v = __float22half2_rn(make_float2(x, y));
    return *reinterpret_cast<uint32_t*>(&v);
}

// ---------------- mask dtype probe ----------------
__global__ void probe_mask(const unsigned char* __restrict__ p) {
    __shared__ int cnt[4];
    if (threadIdx.x < 4) cnt[threadIdx.x] = 0;
    __syncthreads();
    int local[4] = {0, 0, 0, 0};
    for (int i = threadIdx.x; i < 8192; i += blockDim.x)
        if (p[i]) local[i & 3]++;
    #pragma unroll
    for (int c = 0; c < 4; c++)
        if (local[c]) atomicAdd(&cnt[c], local[c]);
    __syncthreads();
    if (threadIdx.x == 0) {
        int c0 = cnt[0], c1 = cnt[1], c2 = cnt[2], c3 = cnt[3];
        int mode = 0;
        if (c0 > 0 && c1 == 0 && c2 == 0 && c3 == 0) mode = 1;
        else if (c0 == 0 && c1 == 0 && (c2 > 0 || c3 > 0)) mode = 2;
        g_mask_mode = mode;
    }
}

// ---------------- fp32 -> fp16 convert ----------------
__global__ __launch_bounds__(256) void convert_h(
    const float* __restrict__ in, __half* __restrict__ h, int n4)
{
    int i = blockIdx.x * blockDim.x + threadIdx.x;
    if (i >= n4) return;
    float4 v = ((const float4*)in)[i];
    __half2 h01 = __float22half2_rn(make_float2(v.x, v.y));
    __half2 h23 = __float22half2_rn(make_float2(v.z, v.w));
    ((__half2*)h)[2*i]   = h01;
    ((__half2*)h)[2*i+1] = h23;
}

// =================================================================
// fp16 HMMA GEMM: C = act(A @ W^T + bias (+R))
// A [M,K], W [N,K] fp16 K-major. 128x128 CTA tile, 4 warps (64x64),
// BK=64, 3-stage cp.async, 128B-row swizzled smem (attention-validated).
// =================================================================
#define STG_T 16384                // bytes/tensor/stage (128 rows * 128B)
#define STG_ALL 32768              // A | W
#define SMEMG (3 * STG_ALL)        // 96 KB

#define LOAD_STAGE(stg, ch) do { \
    const uint32_t _base = sb + (stg) * STG_ALL; \
    const int _ko = (ch) * 64; \
    _Pragma("unroll") \
    for (int i = 0; i < 16; i++) { \
        const int idx = i * 128 + tid; \
        const int t = idx >> 10; \
        const int c = idx & 1023; \
        const int row = c >> 3, g = c & 7; \
        const __half* _s = (t ? gW : gA) + (size_t)row * K + _ko + g * 8; \
        cpa16(_base + t * STG_T + row * 128 \
              + (((uint32_t)(g ^ (row & 7))) << 4), _s); \
    } \
} while (0)

template <int RELU, int RES, int OUTH>
__global__ __launch_bounds__(128) void gemm_f16(
    const __half* __restrict__ A, const __half* __restrict__ W,
    const float* __restrict__ bias, const float* __restrict__ R,
    float* __restrict__ Cf, __half* __restrict__ Ch, int M, int N, int K)
{
    extern __shared__ char smem[];
    const uint32_t sb = smem_u32(smem);
    const int tid = threadIdx.x, lane = tid & 31, wid = tid >> 5;
    const int wm = wid & 1, wn = wid >> 1;
    const int m0 = blockIdx.y * 128, n0 = blockIdx.x * 128;

    const __half* gA = A + (size_t)m0 * K;
    const __half* gW = W + (size_t)n0 * K;

    const int r15 = lane & 15;
    const int hs  = lane >> 4;
    const uint32_t x7 = (uint32_t)(r15 & 7);

    float acc[4][8][4];
    #pragma unroll
    for (int a = 0; a < 4; a++)
        #pragma unroll
        for (int b = 0; b < 8; b++)
            #pragma unroll
            for (int c = 0; c < 4; c++) acc[a][b][c] = 0.f;

    const int nch = K >> 6;

    LOAD_STAGE(0, 0); cpa_commit();
    LOAD_STAGE(1, 1); cpa_commit();

    int stg = 0;
    for (int ch = 0; ch < nch; ch++) {
        cpa_wait1();
        __syncthreads();
        const int nc = ch + 2;
        if (nc < nch) {
            const int ns = (stg == 0) ? 2 : stg - 1;
            LOAD_STAGE(ns, nc);
        }
        cpa_commit();

        const uint32_t st = sb + stg * STG_ALL;
        #pragma unroll
        for (int kk = 0; kk < 4; kk++) {
            const uint32_t ksw = (((uint32_t)(2 * kk + hs)) ^ x7) << 4;
            uint32_t af[4][4], bf[4][4];
            #pragma unroll
            for (int mt = 0; mt < 4; mt++)
                ldsm4(af[mt], st + (uint32_t)(wm * 64 + mt * 16 + r15) * 128 + ksw);
            #pragma unroll
            for (int g = 0; g < 4; g++)
                ldsm4(bf[g], st + STG_T + (uint32_t)(wn * 64 + g * 16 + r15) * 128 + ksw);
            #pragma unroll
            for (int mt = 0; mt < 4; mt++) {
                #pragma unroll
                for (int g = 0; g < 4; g++) {
                    mma16816(acc[mt][2*g],   af[mt], bf[g][0], bf[g][2]);
                    mma16816(acc[mt][2*g+1], af[mt], bf[g][1], bf[g][3]);
                }
            }
        }
        stg = (stg == 2) ? 0 : stg + 1;
    }

    const int gr = lane >> 2;
    const int gc = (lane & 3) * 2;
    #pragma unroll
    for (int mt = 0; mt < 4; mt++) {
        #pragma unroll
        for (int half = 0; half < 2; half++) {
            const int m = m0 + wm * 64 + mt * 16 + gr + half * 8;
            #pragma unroll
            for (int nt = 0; nt < 8; nt++) {
                const int col = n0 + wn * 64 + nt * 8 + gc;
                float2 bv = *(const float2*)(bias + col);
                float ox = acc[mt][nt][2*half + 0] + bv.x;
                float oy = acc[mt][nt][2*half + 1] + bv.y;
                if (RES) {
                    float2 rv = *(const float2*)(R + (size_t)m * N + col);
                    ox += rv.x; oy += rv.y;
                }
                if (RELU) { ox = fmaxf(ox, 0.f); oy = fmaxf(oy, 0.f); }
                if (OUTH) {
                    *(__half2*)(Ch + (size_t)m * N + col) =
                        __float22half2_rn(make_float2(ox, oy));
                } else {
                    *(float2*)(Cf + (size_t)m * N + col) = make_float2(ox, oy);
                }
            }
        }
    }
}

// =================================================================
// fp16 tensor-core flash attention, 2-stage double-buffered K/V.
// 128 threads (4 warps), 64 queries/block, grid (16, 16, 8).
// smem: Q (8 KB) | KV stage0 (16 KB) | KV stage1 (16 KB) | bias[2][64]
// =================================================================
#define AQ 0
#define AKV 8192
#define KVSTG 16384
#define ABIAS (AKV + 2 * KVSTG)     // 40960
#define ATT_SMEM (ABIAS + 512)

#define LOADKV(st_, kt_) do { \
    const int _t0 = (kt_) * 64; \
    const uint32_t _kb = sb + AKV + (st_) * KVSTG; \
    _Pragma("unroll") \
    for (int i = 0; i < 8; i++) { \
        const int idx = i * 128 + tid; \
        const int t2 = idx >> 9; \
        const int c = idx & 511; \
        const int row = c >> 3, g = c & 7; \
        const __half* src = qkv \
            + (size_t)(b * TT + _t0 + row) * row3 \
            + EE + t2 * EE + h * HD + g * 8; \
        cpa16(_kb + t2 * 8192 + row * 128 \
              + (((uint32_t)(g ^ (row & 7))) << 4), src); \
    } \
    if (tid < 64) { \
        const int tk = _t0 + tid; \
        bool pm; \
        if (mode == 1)      pm = (((const int*)pad)[b * TT + tk] != 0); \
        else if (mode == 2) pm = (((const float*)pad)[b * TT + tk] != 0.f); \
        else                pm = (((const unsigned char*)pad)[b * TT + tk] != 0); \
        sbias[((st_) << 6) + tid] = pm ? -1e30f : 0.f; \
    } \
} while (0)

__global__ __launch_bounds__(128) void attn_mma(
    const __half* __restrict__ qkv,
    const void* __restrict__ pad,
    __half* __restrict__ outp)
{
    extern __shared__ char sm[];
    const uint32_t sb = smem_u32(sm);
    float* sbias = (float*)(sm + ABIAS);

    const int tid = threadIdx.x, lane = tid & 31, w = tid >> 5;
    const int qt = (int)gridDim.x - 1 - (int)blockIdx.x;   // LPT
    const int h = blockIdx.y, b = blockIdx.z;
    const int q0 = qt * 64;
    const int row3 = 3 * EE;
    const int mode = g_mask_mode;
    const int gr = lane >> 2;
    const int r15 = lane & 15;
    const int hs = lane >> 4;
    const uint32_t x7 = (uint32_t)(r15 & 7);

    // ---- stage Q, prefetch KV tiles 0 and 1 ----
    #pragma unroll
    for (int i = 0; i < 4; i++) {
        const int idx = i * 128 + tid;
        const int row = idx >> 3, g = idx & 7;
        const __half* src = qkv
            + (size_t)(b * TT + q0 + row) * row3 + h * HD + g * 8;
        cpa16(sb + row * 128 + (((uint32_t)(g ^ (row & 7))) << 4), src);
    }
    cpa_commit();
    LOADKV(0, 0); cpa_commit();
    if (qt >= 1) { LOADKV(1, 1); cpa_commit(); }
    if (qt >= 1) cpa_wait2(); else cpa_wait1();
    __syncthreads();

    uint32_t qf[4][4];
    #pragma unroll
    for (int kc = 0; kc < 4; kc++) {
        const uint32_t a = (uint32_t)(16 * w + r15) * 128
            + ((((uint32_t)(2 * kc + hs)) ^ x7) << 4);
        ldsm4(qf[kc], sb + AQ + a);
    }

    float m2[2] = {-1e30f, -1e30f};
    float lsum[2] = {0.f, 0.f};
    float o[8][4];
    #pragma unroll
    for (int nt = 0; nt < 8; nt++)
        #pragma unroll
        for (int i = 0; i < 4; i++) o[nt][i] = 0.f;

    const float cst = SCALE * 1.44269504f;

    for (int kt = 0; kt <= qt; kt++) {
        if (kt == qt) cpa_wait0(); else cpa_wait1();
        __syncthreads();

        const int st = kt & 1;
        const uint32_t kvb = sb + AKV + st * KVSTG;
        const float* sbst = sbias + (st << 6);
        const int t0 = kt * 64;

        // ---- S = Q K^T ----
        float s[8][4];
        #pragma unroll
        for (int nt = 0; nt < 8; nt++)
            #pragma unroll
            for (int i = 0; i < 4; i++) s[nt][i] = 0.f;

        #pragma unroll
        for (int kc = 0; kc < 4; kc++) {
            const uint32_t ksw = (((uint32_t)(2 * kc + hs)) ^ x7) << 4;
            uint32_t bh[4][4];
            #pragma unroll
            for (int g2 = 0; g2 < 4; g2++)
                ldsm4(bh[g2], kvb + (uint32_t)(16 * g2 + r15) * 128 + ksw);
            #pragma unroll
            for (int g2 = 0; g2 < 4; g2++) {
                mma16816(s[2*g2],   qf[kc], bh[g2][0], bh[g2][2]);
                mma16816(s[2*g2+1], qf[kc], bh[g2][1], bh[g2][3]);
            }
        }

        // ---- softmax (base-2, online) ----
        float ml0 = -1e30f, ml1 = -1e30f;
        const int diag = (kt == qt);
        #pragma unroll
        for (int nt = 0; nt < 8; nt++) {
            #pragma unroll
            for (int i = 0; i < 4; i++) {
                const int col = nt * 8 + 2 * (lane & 3) + (i & 1);
                float v = s[nt][i] * cst + sbst[col];
                if (diag) {
                    const int kg = t0 + col;
                    const int qg = q0 + 16 * w + gr + (i >> 1) * 8;
                    if (kg > qg) v = -1e30f;
                }
                s[nt][i] = v;
                if (i < 2) ml0 = fmaxf(ml0, v); else ml1 = fmaxf(ml1, v);
            }
        }
        ml0 = fmaxf(ml0, __shfl_xor_sync(0xffffffffu, ml0, 1));
        ml0 = fmaxf(ml0, __shfl_xor_sync(0xffffffffu, ml0, 2));
        ml1 = fmaxf(ml1, __shfl_xor_sync(0xffffffffu, ml1, 1));
        ml1 = fmaxf(ml1, __shfl_xor_sync(0xffffffffu, ml1, 2));
        const float mn0 = fmaxf(m2[0], ml0), mn1 = fmaxf(m2[1], ml1);
        const float al0 = ex2f(m2[0] - mn0), al1 = ex2f(m2[1] - mn1);
        m2[0] = mn0; m2[1] = mn1;

        float rs0 = 0.f, rs1 = 0.f;
        #pragma unroll
        for (int nt = 0; nt < 8; nt++) {
            #pragma unroll
            for (int i = 0; i < 4; i++) {
                const float p = ex2f(s[nt][i] - ((i < 2) ? mn0 : mn1));
                s[nt][i] = p;
                if (i < 2) rs0 += p; else rs1 += p;
            }
        }
        rs0 += __shfl_xor_sync(0xffffffffu, rs0, 1);
        rs0 += __shfl_xor_sync(0xffffffffu, rs0, 2);
        rs1 += __shfl_xor_sync(0xffffffffu, rs1, 1);
        rs1 += __shfl_xor_sync(0xffffffffu, rs1, 2);
        lsum[0] = lsum[0] * al0 + rs0;
        lsum[1] = lsum[1] * al1 + rs1;
        #pragma unroll
        for (int nt = 0; nt < 8; nt++) {
            o[nt][0] *= al0; o[nt][1] *= al0;
            o[nt][2] *= al1; o[nt][3] *= al1;
        }

        // ---- P fragments fp16 ----
        uint32_t pa[4][4];
        #pragma unroll
        for (int c = 0; c < 4; c++) {
            #pragma unroll
            for (int j = 0; j < 4; j++) {
                const int nt = 2 * c + (j >> 1);
                const int i0 = (j & 1) * 2;
                pa[c][j] = packh2(s[nt][i0], s[nt][i0 + 1]);
            }
        }

        // ---- O += P V ----
        #pragma unroll
        for (int c = 0; c < 4; c++) {
            uint32_t vh[4][4];
            #pragma unroll
            for (int g2 = 0; g2 < 4; g2++) {
                const uint32_t a = (uint32_t)(16 * c + r15) * 128
                    + ((((uint32_t)(2 * g2 + hs)) ^ x7) << 4);
                ldsm4t(vh[g2], kvb + 8192 + a);
            }
            #pragma unroll
            for (int g2 = 0; g2 < 4; g2++) {
                mma16816(o[2*g2],   pa[c], vh[g2][0], vh[g2][1]);
                mma16816(o[2*g2+1], pa[c], vh[g2][2], vh[g2][3]);
            }
        }

        if (kt + 2 <= qt) {
            __syncthreads();
            LOADKV(st, kt + 2);
            cpa_commit();
        }
    }

    // ---- epilogue ----
    const float inv0 = 1.f / lsum[0], inv1 = 1.f / lsum[1];
    #pragma unroll
    for (int r = 0; r < 2; r++) {
        const int row = q0 + 16 * w + gr + 8 * r;
        const float inv = r ? inv1 : inv0;
        const size_t base = (size_t)(b * TT + row) * EE + h * HD + 2 * (lane & 3);
        #pragma unroll
        for (int nt = 0; nt < 8; nt++) {
            *(__half2*)(outp + base + nt * 8) = __float22half2_rn(
                make_float2(o[nt][2*r] * inv, o[nt][2*r + 1] * inv));
        }
    }
}

// ---------------- LayerNorm in-place (+ optional fp16 emit) ----------------
template <int HL>
__global__ __launch_bounds__(256) void ln_kernel(
    float* __restrict__ X, const float* __restrict__ w,
    const float* __restrict__ bias, __half* __restrict__ Yh)
{
    __shared__ float red[8];
    const int row = blockIdx.x, tid = threadIdx.x;
    float4* xr = (float4*)(X + (size_t)row * EE);
    float4 v = xr[tid];

    float s = v.x + v.y + v.z + v.w;
    #pragma unroll
    for (int o = 16; o; o >>= 1) s += __shfl_xor_sync(0xffffffffu, s, o);
    if ((tid & 31) == 0) red[tid >> 5] = s;
    __syncthreads();
    float tot = red[0] + red[1] + red[2] + red[3] + red[4] + red[5] + red[6] + red[7];
    const float mean = tot * (1.f / EE);

    float dx = v.x - mean, dy = v.y - mean, dz = v.z - mean, dw = v.w - mean;
    float s2 = dx * dx + dy * dy + dz * dz + dw * dw;
    __syncthreads();
    #pragma unroll
    for (int o = 16; o; o >>= 1) s2 += __shfl_xor_sync(0xffffffffu, s2, o);
    if ((tid & 31) == 0) red[tid >> 5] = s2;
    __syncthreads();
    float tot2 = red[0] + red[1] + red[2] + red[3] + red[4] + red[5] + red[6] + red[7];
    const float var = tot2 * (1.f / EE);
    const float inv = rsqrtf(var + 1e-12f);

    float4 wv = ((const float4*)w)[tid];
    float4 bv = ((const float4*)bias)[tid];
    float4 r;
    r.x = dx * inv * wv.x + bv.x;
    r.y = dy * inv * wv.y + bv.y;
    r.z = dz * inv * wv.z + bv.z;
    r.w = dw * inv * wv.w + bv.w;
    xr[tid] = r;
    if (HL) {
        const size_t base = (size_t)row * EE + tid * 4;
        *(__half2*)(Yh + base)     = __float22half2_rn(make_float2(r.x, r.y));
        *(__half2*)(Yh + base + 2) = __float22half2_rn(make_float2(r.z, r.w));
    }
}

// ---------------- launch ----------------
extern "C" void kernel_launch(void* const* d_in, const int* in_sizes, int n_in,
                              void* d_out, int out_size)
{
    const float* x     = (const float*)d_in[0];
    const float* in_w  = (const float*)d_in[1];
    const float* in_b  = (const float*)d_in[2];
    const float* out_w = (const float*)d_in[3];
    const float* out_b = (const float*)d_in[4];
    const float* fc1_w = (const float*)d_in[5];
    const float* fc1_b = (const float*)d_in[6];
    const float* fc2_w = (const float*)d_in[7];
    const float* fc2_b = (const float*)d_in[8];
    const float* ln1_w = (const float*)d_in[9];
    const float* ln1_b = (const float*)d_in[10];
    const float* ln2_w = (const float*)d_in[11];
    const float* ln2_b = (const float*)d_in[12];
    const void*  pad   = d_in[13];
    float* out = (float*)d_out;

    float* p_y1;
    __half *p_q, *p_x, *p_a, *p_y1h, *p_f, *p_wi, *p_wo, *p_w1, *p_w2;
    cudaGetSymbolAddress((void**)&p_y1,  g_y1);
    cudaGetSymbolAddress((void**)&p_q,   g_q);
    cudaGetSymbolAddress((void**)&p_x,   g_x);
    cudaGetSymbolAddress((void**)&p_a,   g_a);
    cudaGetSymbolAddress((void**)&p_y1h, g_y1h);
    cudaGetSymbolAddress((void**)&p_f,   g_f);
    cudaGetSymbolAddress((void**)&p_wi,  g_wi);
    cudaGetSymbolAddress((void**)&p_wo,  g_wo);
    cudaGetSymbolAddress((void**)&p_w1,  g_w1);
    cudaGetSymbolAddress((void**)&p_w2,  g_w2);

    cudaFuncSetAttribute(gemm_f16<0,0,1>, cudaFuncAttributeMaxDynamicSharedMemorySize, SMEMG);
    cudaFuncSetAttribute(gemm_f16<0,1,0>, cudaFuncAttributeMaxDynamicSharedMemorySize, SMEMG);
    cudaFuncSetAttribute(gemm_f16<1,0,1>, cudaFuncAttributeMaxDynamicSharedMemorySize, SMEMG);
    cudaFuncSetAttribute(attn_mma, cudaFuncAttributeMaxDynamicSharedMemorySize, ATT_SMEM);

    probe_mask<<<1, 256>>>((const unsigned char*)pad);

    convert_h<<<(MM * EE / 4 + 255) / 256, 256>>>(x, p_x, MM * EE / 4);
    convert_h<<<(3 * EE * EE / 4 + 255) / 256, 256>>>(in_w,  p_wi, 3 * EE * EE / 4);
    convert_h<<<(EE * EE / 4 + 255) / 256, 256>>>(out_w, p_wo, EE * EE / 4);
    convert_h<<<(FFD * EE / 4 + 255) / 256, 256>>>(fc1_w, p_w1, FFD * EE / 4);
    convert_h<<<(EE * FFD / 4 + 255) / 256, 256>>>(fc2_w, p_w2, EE * FFD / 4);

    // 1. QKV projection -> fp16
    gemm_f16<0,0,1><<<dim3(3 * EE / 128, MM / 128), 128, SMEMG>>>(
        p_x, p_wi, in_b, nullptr, nullptr, p_q, MM, 3 * EE, EE);

    // 2. fp16 flash attention -> fp16
    attn_mma<<<dim3(TT / 64, HH, BB), 128, ATT_SMEM>>>(p_q, pad, p_a);

    // 3. out projection + bias + residual(x) -> fp32 y1
    gemm_f16<0,1,0><<<dim3(EE / 128, MM / 128), 128, SMEMG>>>(
        p_a, p_wo, out_b, x, p_y1, nullptr, MM, EE, EE);

    // 4. LN1 in-place + fp16 emit
    ln_kernel<1><<<MM, 256>>>(p_y1, ln1_w, ln1_b, p_y1h);

    // 5. FC1 + ReLU -> fp16
    gemm_f16<1,0,1><<<dim3(FFD / 128, MM / 128), 128, SMEMG>>>(
        p_y1h, p_w1, fc1_b, nullptr, nullptr, p_f, MM, FFD, EE);

    // 6. FC2 + bias + residual(y1) -> d_out fp32
    gemm_f16<0,1,0><<<dim3(EE / 128, MM / 128), 128, SMEMG>>>(
        p_f, p_w2, fc2_b, p_y1, out, nullptr, MM, EE, FFD);

    // 7. LN2 in-place on d_out
    ln_kernel<0><<<MM, 256>>>(out, ln2_w, ln2_b, nullptr);
}